// round 4
// baseline (speedup 1.0000x reference)
#include <cuda_runtime.h>
#include <mma.h>
#include <math.h>

using namespace nvcuda;

#define DM 1024
#define NH 16
#define HD 64
#define B_ 2
#define T_ 2048
#define ROWS (B_*T_)

#define BR 128
#define BC 64
#define LDF 68          // flash smem row pitch (floats)

// Scratch (static device globals — allocation-free per harness rules)
__device__ float g_q[(size_t)B_*NH*T_*HD];     // [B,H,T,hd]
__device__ float g_k[(size_t)B_*NH*T_*HD];
__device__ float g_v[(size_t)B_*NH*T_*HD];
__device__ float g_attn[(size_t)ROWS*DM];      // [B,T,D]

__device__ __forceinline__ float ftf(float x) { return wmma::__float_to_tf32(x); }

// ---------------------------------------------------------------------------
// tf32 wmma GEMM body: C[M,N]=A[M,K]@B[K,N]. 128x128 tile, BK=32, 8 warps,
// register-prefetch double buffering to hide gmem latency behind MMAs.
// ---------------------------------------------------------------------------
__device__ __forceinline__
void gemm_body(const float* __restrict__ A, const float* __restrict__ Bw,
               float* __restrict__ C, bool splitHeads)
{
    __shared__ float As[128][36];
    __shared__ float Bs[32][132];
    const int K = 1024, N = 1024;
    const int tid = threadIdx.x;
    const int wid = tid >> 5;
    const int warp_m = wid >> 2, warp_n = wid & 3;
    const int bm = blockIdx.y << 7, bn = blockIdx.x << 7;

    const int ar = tid >> 3, ac = (tid & 7) << 2;    // A: +t*32 rows, 8 f4/row
    const int br = tid >> 5, bc = (tid & 31) << 2;   // B: +t*8 rows, 32 f4/row

    wmma::fragment<wmma::accumulator, 16, 16, 8, float> acc[4][2];
#pragma unroll
    for (int i = 0; i < 4; i++)
#pragma unroll
        for (int j = 0; j < 2; j++) wmma::fill_fragment(acc[i][j], 0.0f);

    float4 a_pre[4], b_pre[4];
#pragma unroll
    for (int t = 0; t < 4; t++) {
        a_pre[t] = *(const float4*)&A[(size_t)(bm + ar + t * 32) * K + ac];
        b_pre[t] = *(const float4*)&Bw[(size_t)(br + t * 8) * N + bn + bc];
    }

    for (int k0 = 0; k0 < K; k0 += 32) {
#pragma unroll
        for (int t = 0; t < 4; t++) {
            float4 a4 = a_pre[t], b4 = b_pre[t];
            *(float4*)&As[ar + t * 32][ac] =
                make_float4(ftf(a4.x), ftf(a4.y), ftf(a4.z), ftf(a4.w));
            *(float4*)&Bs[br + t * 8][bc] =
                make_float4(ftf(b4.x), ftf(b4.y), ftf(b4.z), ftf(b4.w));
        }
        __syncthreads();
        if (k0 + 32 < K) {
            int kn = k0 + 32;
#pragma unroll
            for (int t = 0; t < 4; t++) {
                a_pre[t] = *(const float4*)&A[(size_t)(bm + ar + t * 32) * K + kn + ac];
                b_pre[t] = *(const float4*)&Bw[(size_t)(kn + br + t * 8) * N + bn + bc];
            }
        }
#pragma unroll
        for (int ks = 0; ks < 4; ks++) {
            wmma::fragment<wmma::matrix_a, 16, 16, 8, wmma::precision::tf32, wmma::row_major> af[4];
            wmma::fragment<wmma::matrix_b, 16, 16, 8, wmma::precision::tf32, wmma::row_major> bf[2];
#pragma unroll
            for (int i = 0; i < 4; i++)
                wmma::load_matrix_sync(af[i], &As[warp_m * 64 + i * 16][ks * 8], 36);
#pragma unroll
            for (int j = 0; j < 2; j++)
                wmma::load_matrix_sync(bf[j], &Bs[ks * 8][warp_n * 32 + j * 16], 132);
#pragma unroll
            for (int i = 0; i < 4; i++)
#pragma unroll
                for (int j = 0; j < 2; j++)
                    wmma::mma_sync(acc[i][j], af[i], bf[j], acc[i][j]);
        }
        __syncthreads();
    }

#pragma unroll
    for (int i = 0; i < 4; i++)
#pragma unroll
        for (int j = 0; j < 2; j++) {
            int m0 = bm + warp_m * 64 + i * 16;
            int n0 = bn + warp_n * 32 + j * 16;
            if (splitHeads) {
                int b = m0 >> 11, t = m0 & (T_ - 1);
                int h = n0 >> 6, d = n0 & (HD - 1);
                float* p = C + ((size_t)(b * NH + h) * T_ + t) * HD + d;
                wmma::store_matrix_sync(p, acc[i][j], HD, wmma::mem_row_major);
            } else {
                wmma::store_matrix_sync(C + (size_t)m0 * N + n0, acc[i][j], N,
                                        wmma::mem_row_major);
            }
        }
}

__global__ __launch_bounds__(256)
void qkv_gemm(const float* __restrict__ X,
              const float* __restrict__ Wq, const float* __restrict__ Wk,
              const float* __restrict__ Wv,
              float* __restrict__ Q, float* __restrict__ K, float* __restrict__ V)
{
    const float* W; float* C;
    if (blockIdx.z == 0)      { W = Wq; C = Q; }
    else if (blockIdx.z == 1) { W = Wk; C = K; }
    else                      { W = Wv; C = V; }
    gemm_body(X, W, C, true);
}

__global__ __launch_bounds__(256)
void oproj_gemm(const float* __restrict__ A, const float* __restrict__ W,
                float* __restrict__ C)
{
    gemm_body(A, W, C, false);
}

// ---------------------------------------------------------------------------
// Fused per-head RMSNorm + RoPE, in place on [B,H,T,hd]. One warp per row.
// ---------------------------------------------------------------------------
__global__ __launch_bounds__(256)
void rmsrope_kernel(float* __restrict__ X, const float* __restrict__ w)
{
    int row = blockIdx.x * 8 + (threadIdx.x >> 5);
    int lane = threadIdx.x & 31;
    float* p = X + (size_t)row * HD;
    float x1 = p[lane], x2 = p[lane + 32];
    float ss = x1 * x1 + x2 * x2;
#pragma unroll
    for (int off = 16; off; off >>= 1)
        ss += __shfl_xor_sync(0xffffffffu, ss, off);
    float rms = rsqrtf(ss * (1.0f / HD) + 1e-6f);
    float n1 = x1 * rms * w[lane];
    float n2 = x2 * rms * w[lane + 32];
    int t = row & (T_ - 1);
    float freq = (float)t * powf(10000.0f, -(float)(2 * lane) * (1.0f / HD));
    float sn, cs;
    sincosf(freq, &sn, &cs);
    p[lane]      = n1 * cs - n2 * sn;
    p[lane + 32] = n2 * cs + n1 * sn;
}

// ---------------------------------------------------------------------------
// Flash attention, tf32 wmma, causal. Br=128 x Bc=64, 8 warps, 2 CTAs/SM.
// Warp w owns rows [16w,16w+16); thread owns half-row (32 floats) of O in regs.
// ---------------------------------------------------------------------------
extern __shared__ float fsm[];
__global__ __launch_bounds__(256, 2)
void flash_kernel(const float* __restrict__ Q, const float* __restrict__ K,
                  const float* __restrict__ V, float* __restrict__ O)
{
    float* Qs = fsm;                          // BR*LDF
    float* Ks = Qs + BR * LDF;                // BC*LDF
    float* Vs = Ks + BC * LDF;                // BC*LDF
    float* Ss = Vs + BC * LDF;                // BR*LDF (S, then P, then PV)

    const int tid = threadIdx.x;
    const int wid = tid >> 5;
    const int qt = gridDim.x - 1 - blockIdx.x;   // heavy tiles first
    const int q0 = qt << 7;
    const int bh = blockIdx.y;
    const float* Qg = Q + ((size_t)bh * T_ + q0) * HD;
    const float* Kg = K + (size_t)bh * T_ * HD;
    const float* Vg = V + (size_t)bh * T_ * HD;

    // Load Q tile (tf32)
    for (int f = tid; f < BR * HD / 4; f += 256) {
        int r = f >> 4, c = (f & 15) << 2;
        float4 q4 = *(const float4*)&Qg[(size_t)r * HD + c];
        *(float4*)&Qs[r * LDF + c] = make_float4(ftf(q4.x), ftf(q4.y), ftf(q4.z), ftf(q4.w));
    }

    const int rown = tid >> 1;            // row this thread owns (== warp strip)
    const int c0 = (tid & 1) << 5;        // half-row offset
    float m_r = -1e30f, l_r = 0.f;
    float o_reg[32];
#pragma unroll
    for (int c = 0; c < 32; c++) o_reg[c] = 0.f;
    const int nkt = 2 * (qt + 1);

    for (int kt = 0; kt < nkt; kt++) {
        const int k0 = kt << 6;
        __syncthreads();
        // Load K,V tiles (tf32)
        for (int f = tid; f < BC * HD / 4; f += 256) {
            int r = f >> 4, c = (f & 15) << 2;
            float4 k4 = *(const float4*)&Kg[(size_t)(k0 + r) * HD + c];
            float4 v4 = *(const float4*)&Vg[(size_t)(k0 + r) * HD + c];
            *(float4*)&Ks[r * LDF + c] = make_float4(ftf(k4.x), ftf(k4.y), ftf(k4.z), ftf(k4.w));
            *(float4*)&Vs[r * LDF + c] = make_float4(ftf(v4.x), ftf(v4.y), ftf(v4.z), ftf(v4.w));
        }
        __syncthreads();

        // S = Q @ K^T  (warp strip 16 x 64)
        {
            wmma::fragment<wmma::accumulator, 16, 16, 8, float> s[4];
#pragma unroll
            for (int c = 0; c < 4; c++) wmma::fill_fragment(s[c], 0.0f);
#pragma unroll
            for (int d0 = 0; d0 < HD; d0 += 8) {
                wmma::fragment<wmma::matrix_a, 16, 16, 8, wmma::precision::tf32, wmma::row_major> af;
                wmma::load_matrix_sync(af, &Qs[(wid * 16) * LDF + d0], LDF);
#pragma unroll
                for (int c = 0; c < 4; c++) {
                    wmma::fragment<wmma::matrix_b, 16, 16, 8, wmma::precision::tf32, wmma::col_major> bf;
                    wmma::load_matrix_sync(bf, &Ks[(c * 16) * LDF + d0], LDF);
                    wmma::mma_sync(s[c], af, bf, s[c]);
                }
            }
#pragma unroll
            for (int c = 0; c < 4; c++)
                wmma::store_matrix_sync(&Ss[(wid * 16) * LDF + c * 16], s[c], LDF,
                                        wmma::mem_row_major);
        }
        __syncwarp();

        // Online softmax on the owned half-row (two passes over smem)
        float alpha;
        {
            const int lim = q0 + rown - k0;   // valid keys: c0+c <= lim
            float mx = -1e30f;
#pragma unroll
            for (int c = 0; c < 32; c++) {
                float s = (c0 + c <= lim) ? Ss[rown * LDF + c0 + c] * 0.125f : -1e30f;
                mx = fmaxf(mx, s);
            }
            mx = fmaxf(mx, __shfl_xor_sync(0xffffffffu, mx, 1));
            float newm = fmaxf(m_r, mx);
            alpha = __expf(m_r - newm);
            m_r = newm;
            float sum = 0.f;
#pragma unroll
            for (int c = 0; c < 32; c++) {
                float p = (c0 + c <= lim)
                        ? __expf(Ss[rown * LDF + c0 + c] * 0.125f - newm) : 0.f;
                sum += p;
                Ss[rown * LDF + c0 + c] = ftf(p);
            }
            sum += __shfl_xor_sync(0xffffffffu, sum, 1);
            l_r = l_r * alpha + sum;
        }
        __syncwarp();

        // PV (warp strip 16 x 64), result back into Ss strip
        {
            wmma::fragment<wmma::accumulator, 16, 16, 8, float> pv[4];
#pragma unroll
            for (int c = 0; c < 4; c++) wmma::fill_fragment(pv[c], 0.0f);
#pragma unroll
            for (int kk = 0; kk < BC; kk += 8) {
                wmma::fragment<wmma::matrix_a, 16, 16, 8, wmma::precision::tf32, wmma::row_major> af;
                wmma::load_matrix_sync(af, &Ss[(wid * 16) * LDF + kk], LDF);
#pragma unroll
                for (int c = 0; c < 4; c++) {
                    wmma::fragment<wmma::matrix_b, 16, 16, 8, wmma::precision::tf32, wmma::row_major> bf;
                    wmma::load_matrix_sync(bf, &Vs[kk * LDF + c * 16], LDF);
                    wmma::mma_sync(pv[c], af, bf, pv[c]);
                }
            }
            __syncwarp();
#pragma unroll
            for (int c = 0; c < 4; c++)
                wmma::store_matrix_sync(&Ss[(wid * 16) * LDF + c * 16], pv[c], LDF,
                                        wmma::mem_row_major);
        }
        __syncwarp();

        // O = O*alpha + PV on owned half-row (registers)
#pragma unroll
        for (int c = 0; c < 32; c++)
            o_reg[c] = o_reg[c] * alpha + Ss[rown * LDF + c0 + c];
    }

    // Epilogue: normalize, write to [B,T,D]
    const int b = bh >> 4, h = bh & (NH - 1);
    const float inv = 1.0f / l_r;
    float* Og = O + ((size_t)(b * T_ + q0 + rown)) * DM + h * HD + c0;
#pragma unroll
    for (int c = 0; c < 32; c += 4) {
        float4 o = make_float4(o_reg[c] * inv, o_reg[c + 1] * inv,
                               o_reg[c + 2] * inv, o_reg[c + 3] * inv);
        *(float4*)&Og[c] = o;
    }
}

// ---------------------------------------------------------------------------
extern "C" void kernel_launch(void* const* d_in, const int* in_sizes, int n_in,
                              void* d_out, int out_size)
{
    (void)in_sizes; (void)n_in; (void)out_size;
    const float* x  = (const float*)d_in[0];
    const float* Wq = (const float*)d_in[1];
    const float* Wk = (const float*)d_in[2];
    const float* Wv = (const float*)d_in[3];
    const float* Wo = (const float*)d_in[4];
    const float* qw = (const float*)d_in[5];
    const float* kw = (const float*)d_in[6];
    float* out = (float*)d_out;

    float *qp, *kp, *vp, *ap;
    cudaGetSymbolAddress((void**)&qp, g_q);
    cudaGetSymbolAddress((void**)&kp, g_k);
    cudaGetSymbolAddress((void**)&vp, g_v);
    cudaGetSymbolAddress((void**)&ap, g_attn);

    const int FLASH_SMEM = (2 * BR * LDF + 2 * BC * LDF) * 4;   // 104448 B
    cudaFuncSetAttribute(flash_kernel,
                         cudaFuncAttributeMaxDynamicSharedMemorySize, FLASH_SMEM);

    dim3 gq(DM / 128, ROWS / 128, 3);   // (8, 32, 3)
    qkv_gemm<<<gq, 256>>>(x, Wq, Wk, Wv, qp, kp, vp);

    rmsrope_kernel<<<B_ * NH * T_ / 8, 256>>>(qp, qw);
    rmsrope_kernel<<<B_ * NH * T_ / 8, 256>>>(kp, kw);

    flash_kernel<<<dim3(T_ / BR, B_ * NH), 256, FLASH_SMEM>>>(qp, kp, vp, ap);

    dim3 go(DM / 128, ROWS / 128);      // (8, 32)
    oproj_gemm<<<go, 256>>>(ap, Wo, out);
}

// round 5
// speedup vs baseline: 1.0947x; 1.0947x over previous
#include <cuda_runtime.h>
#include <mma.h>
#include <math.h>

using namespace nvcuda;

#define DM 1024
#define NH 16
#define HD 64
#define B_ 2
#define T_ 2048
#define ROWS (B_*T_)

#define BR 128
#define BC 64
#define LDF 68          // flash smem row pitch (floats)

// GEMM smem layout (floats): two stages of As[128][36] + Bs[32][132]
#define AS_STRIDE (128*36)
#define BS_STRIDE (32*132)
#define GEMM_SMEM_FLOATS (2*AS_STRIDE + 2*BS_STRIDE)

// Scratch (static device globals — allocation-free per harness rules)
__device__ float g_q[(size_t)B_*NH*T_*HD];     // [B,H,T,hd]
__device__ float g_k[(size_t)B_*NH*T_*HD];
__device__ float g_v[(size_t)B_*NH*T_*HD];
__device__ float g_attn[(size_t)ROWS*DM];      // [B,T,D]

__device__ __forceinline__ float ftf(float x) { return wmma::__float_to_tf32(x); }

__device__ __forceinline__ void cp_async16(void* smem_ptr, const void* gmem_ptr) {
    unsigned int saddr = (unsigned int)__cvta_generic_to_shared(smem_ptr);
    asm volatile("cp.async.cg.shared.global [%0], [%1], 16;\n"
                 :: "r"(saddr), "l"(gmem_ptr));
}
__device__ __forceinline__ void cp_commit() {
    asm volatile("cp.async.commit_group;\n");
}
template<int N>
__device__ __forceinline__ void cp_wait() {
    asm volatile("cp.async.wait_group %0;\n" :: "n"(N));
}

// ---------------------------------------------------------------------------
// tf32 wmma GEMM body: C[M,N]=A[M,K]@B[K,N]. 128x128 tile, BK=32, 8 warps,
// 2-stage cp.async smem pipeline; tf32 RN conversion applied on fragments.
// ---------------------------------------------------------------------------
extern __shared__ float gsm[];

__device__ __forceinline__
void gemm_issue_stage(const float* __restrict__ A, const float* __restrict__ Bw,
                      float* As, float* Bs, int bm, int bn, int k0, int tid)
{
    const int K = 1024, N = 1024;
#pragma unroll
    for (int t = 0; t < 4; t++) {
        int f = tid + (t << 8);
        int ar = f >> 3, ac = (f & 7) << 2;       // A: 128 rows x 32 cols
        cp_async16(&As[ar * 36 + ac], &A[(size_t)(bm + ar) * K + k0 + ac]);
        int br = f >> 5, bc = (f & 31) << 2;      // B: 32 rows x 128 cols
        cp_async16(&Bs[br * 132 + bc], &Bw[(size_t)(k0 + br) * N + bn + bc]);
    }
    cp_commit();
}

__device__ __forceinline__
void gemm_body(const float* __restrict__ A, const float* __restrict__ Bw,
               float* __restrict__ C, bool splitHeads)
{
    float* As = gsm;                          // [2][128][36]
    float* Bs = gsm + 2 * AS_STRIDE;          // [2][32][132]
    const int N = 1024;
    const int tid = threadIdx.x;
    const int wid = tid >> 5;
    const int warp_m = wid >> 2, warp_n = wid & 3;
    const int bm = blockIdx.y << 7, bn = blockIdx.x << 7;

    wmma::fragment<wmma::accumulator, 16, 16, 8, float> acc[4][2];
#pragma unroll
    for (int i = 0; i < 4; i++)
#pragma unroll
        for (int j = 0; j < 2; j++) wmma::fill_fragment(acc[i][j], 0.0f);

    gemm_issue_stage(A, Bw, As, Bs, bm, bn, 0, tid);

    for (int it = 0; it < 32; it++) {
        const int s = it & 1;
        if (it + 1 < 32) {
            gemm_issue_stage(A, Bw, As + (s ^ 1) * AS_STRIDE,
                             Bs + (s ^ 1) * BS_STRIDE, bm, bn, (it + 1) * 32, tid);
            cp_wait<1>();
        } else {
            cp_wait<0>();
        }
        __syncthreads();

        float* Asd = As + s * AS_STRIDE;
        float* Bsd = Bs + s * BS_STRIDE;
#pragma unroll
        for (int ks = 0; ks < 4; ks++) {
            wmma::fragment<wmma::matrix_a, 16, 16, 8, wmma::precision::tf32, wmma::row_major> af[4];
            wmma::fragment<wmma::matrix_b, 16, 16, 8, wmma::precision::tf32, wmma::row_major> bf[2];
#pragma unroll
            for (int i = 0; i < 4; i++) {
                wmma::load_matrix_sync(af[i], &Asd[(warp_m * 64 + i * 16) * 36 + ks * 8], 36);
#pragma unroll
                for (int e = 0; e < af[i].num_elements; e++) af[i].x[e] = ftf(af[i].x[e]);
            }
#pragma unroll
            for (int j = 0; j < 2; j++) {
                wmma::load_matrix_sync(bf[j], &Bsd[(ks * 8) * 132 + warp_n * 32 + j * 16], 132);
#pragma unroll
                for (int e = 0; e < bf[j].num_elements; e++) bf[j].x[e] = ftf(bf[j].x[e]);
            }
#pragma unroll
            for (int i = 0; i < 4; i++)
#pragma unroll
                for (int j = 0; j < 2; j++)
                    wmma::mma_sync(acc[i][j], af[i], bf[j], acc[i][j]);
        }
        __syncthreads();
    }

#pragma unroll
    for (int i = 0; i < 4; i++)
#pragma unroll
        for (int j = 0; j < 2; j++) {
            int m0 = bm + warp_m * 64 + i * 16;
            int n0 = bn + warp_n * 32 + j * 16;
            if (splitHeads) {
                int b = m0 >> 11, t = m0 & (T_ - 1);
                int h = n0 >> 6, d = n0 & (HD - 1);
                float* p = C + ((size_t)(b * NH + h) * T_ + t) * HD + d;
                wmma::store_matrix_sync(p, acc[i][j], HD, wmma::mem_row_major);
            } else {
                wmma::store_matrix_sync(C + (size_t)m0 * N + n0, acc[i][j], N,
                                        wmma::mem_row_major);
            }
        }
}

__global__ __launch_bounds__(256, 2)
void qkv_gemm(const float* __restrict__ X,
              const float* __restrict__ Wq, const float* __restrict__ Wk,
              const float* __restrict__ Wv,
              float* __restrict__ Q, float* __restrict__ K, float* __restrict__ V)
{
    const float* W; float* C;
    if (blockIdx.z == 0)      { W = Wq; C = Q; }
    else if (blockIdx.z == 1) { W = Wk; C = K; }
    else                      { W = Wv; C = V; }
    gemm_body(X, W, C, true);
}

__global__ __launch_bounds__(256, 2)
void oproj_gemm(const float* __restrict__ A, const float* __restrict__ W,
                float* __restrict__ C)
{
    gemm_body(A, W, C, false);
}

// ---------------------------------------------------------------------------
// Fused per-head RMSNorm + RoPE, in place on [B,H,T,hd]. One warp per row.
// ---------------------------------------------------------------------------
__global__ __launch_bounds__(256)
void rmsrope_kernel(float* __restrict__ X, const float* __restrict__ w)
{
    int row = blockIdx.x * 8 + (threadIdx.x >> 5);
    int lane = threadIdx.x & 31;
    float* p = X + (size_t)row * HD;
    float x1 = p[lane], x2 = p[lane + 32];
    float ss = x1 * x1 + x2 * x2;
#pragma unroll
    for (int off = 16; off; off >>= 1)
        ss += __shfl_xor_sync(0xffffffffu, ss, off);
    float rms = rsqrtf(ss * (1.0f / HD) + 1e-6f);
    float n1 = x1 * rms * w[lane];
    float n2 = x2 * rms * w[lane + 32];
    int t = row & (T_ - 1);
    float freq = (float)t * powf(10000.0f, -(float)(2 * lane) * (1.0f / HD));
    float sn, cs;
    sincosf(freq, &sn, &cs);
    p[lane]      = n1 * cs - n2 * sn;
    p[lane + 32] = n2 * cs + n1 * sn;
}

// ---------------------------------------------------------------------------
// Flash attention, tf32 wmma, causal. Br=128 x Bc=64, 8 warps, 2 CTAs/SM.
// Warp w owns rows [16w,16w+16); thread owns half-row (32 floats) of O in regs.
// ---------------------------------------------------------------------------
extern __shared__ float fsm[];
__global__ __launch_bounds__(256, 2)
void flash_kernel(const float* __restrict__ Q, const float* __restrict__ K,
                  const float* __restrict__ V, float* __restrict__ O)
{
    float* Qs = fsm;                          // BR*LDF
    float* Ks = Qs + BR * LDF;                // BC*LDF
    float* Vs = Ks + BC * LDF;                // BC*LDF
    float* Ss = Vs + BC * LDF;                // BR*LDF (S, then P, then PV)

    const int tid = threadIdx.x;
    const int wid = tid >> 5;
    const int qt = gridDim.x - 1 - blockIdx.x;   // heavy tiles first
    const int q0 = qt << 7;
    const int bh = blockIdx.y;
    const float* Qg = Q + ((size_t)bh * T_ + q0) * HD;
    const float* Kg = K + (size_t)bh * T_ * HD;
    const float* Vg = V + (size_t)bh * T_ * HD;

    // Load Q tile (tf32)
    for (int f = tid; f < BR * HD / 4; f += 256) {
        int r = f >> 4, c = (f & 15) << 2;
        float4 q4 = *(const float4*)&Qg[(size_t)r * HD + c];
        *(float4*)&Qs[r * LDF + c] = make_float4(ftf(q4.x), ftf(q4.y), ftf(q4.z), ftf(q4.w));
    }

    const int rown = tid >> 1;            // row this thread owns (== warp strip)
    const int c0 = (tid & 1) << 5;        // half-row offset
    float m_r = -1e30f, l_r = 0.f;
    float o_reg[32];
#pragma unroll
    for (int c = 0; c < 32; c++) o_reg[c] = 0.f;
    const int nkt = 2 * (qt + 1);

    for (int kt = 0; kt < nkt; kt++) {
        const int k0 = kt << 6;
        __syncthreads();
        // Load K,V tiles (tf32)
        for (int f = tid; f < BC * HD / 4; f += 256) {
            int r = f >> 4, c = (f & 15) << 2;
            float4 k4 = *(const float4*)&Kg[(size_t)(k0 + r) * HD + c];
            float4 v4 = *(const float4*)&Vg[(size_t)(k0 + r) * HD + c];
            *(float4*)&Ks[r * LDF + c] = make_float4(ftf(k4.x), ftf(k4.y), ftf(k4.z), ftf(k4.w));
            *(float4*)&Vs[r * LDF + c] = make_float4(ftf(v4.x), ftf(v4.y), ftf(v4.z), ftf(v4.w));
        }
        __syncthreads();

        // S = Q @ K^T  (warp strip 16 x 64)
        {
            wmma::fragment<wmma::accumulator, 16, 16, 8, float> s[4];
#pragma unroll
            for (int c = 0; c < 4; c++) wmma::fill_fragment(s[c], 0.0f);
#pragma unroll
            for (int d0 = 0; d0 < HD; d0 += 8) {
                wmma::fragment<wmma::matrix_a, 16, 16, 8, wmma::precision::tf32, wmma::row_major> af;
                wmma::load_matrix_sync(af, &Qs[(wid * 16) * LDF + d0], LDF);
#pragma unroll
                for (int c = 0; c < 4; c++) {
                    wmma::fragment<wmma::matrix_b, 16, 16, 8, wmma::precision::tf32, wmma::col_major> bf;
                    wmma::load_matrix_sync(bf, &Ks[(c * 16) * LDF + d0], LDF);
                    wmma::mma_sync(s[c], af, bf, s[c]);
                }
            }
#pragma unroll
            for (int c = 0; c < 4; c++)
                wmma::store_matrix_sync(&Ss[(wid * 16) * LDF + c * 16], s[c], LDF,
                                        wmma::mem_row_major);
        }
        __syncwarp();

        // Online softmax on the owned half-row (two passes over smem)
        float alpha;
        {
            const int lim = q0 + rown - k0;   // valid keys: c0+c <= lim
            float mx = -1e30f;
#pragma unroll
            for (int c = 0; c < 32; c++) {
                float s = (c0 + c <= lim) ? Ss[rown * LDF + c0 + c] * 0.125f : -1e30f;
                mx = fmaxf(mx, s);
            }
            mx = fmaxf(mx, __shfl_xor_sync(0xffffffffu, mx, 1));
            float newm = fmaxf(m_r, mx);
            alpha = __expf(m_r - newm);
            m_r = newm;
            float sum = 0.f;
#pragma unroll
            for (int c = 0; c < 32; c++) {
                float p = (c0 + c <= lim)
                        ? __expf(Ss[rown * LDF + c0 + c] * 0.125f - newm) : 0.f;
                sum += p;
                Ss[rown * LDF + c0 + c] = ftf(p);
            }
            sum += __shfl_xor_sync(0xffffffffu, sum, 1);
            l_r = l_r * alpha + sum;
        }
        __syncwarp();

        // PV (warp strip 16 x 64), result back into Ss strip
        {
            wmma::fragment<wmma::accumulator, 16, 16, 8, float> pv[4];
#pragma unroll
            for (int c = 0; c < 4; c++) wmma::fill_fragment(pv[c], 0.0f);
#pragma unroll
            for (int kk = 0; kk < BC; kk += 8) {
                wmma::fragment<wmma::matrix_a, 16, 16, 8, wmma::precision::tf32, wmma::row_major> af;
                wmma::load_matrix_sync(af, &Ss[(wid * 16) * LDF + kk], LDF);
#pragma unroll
                for (int c = 0; c < 4; c++) {
                    wmma::fragment<wmma::matrix_b, 16, 16, 8, wmma::precision::tf32, wmma::row_major> bf;
                    wmma::load_matrix_sync(bf, &Vs[kk * LDF + c * 16], LDF);
                    wmma::mma_sync(pv[c], af, bf, pv[c]);
                }
            }
            __syncwarp();
#pragma unroll
            for (int c = 0; c < 4; c++)
                wmma::store_matrix_sync(&Ss[(wid * 16) * LDF + c * 16], pv[c], LDF,
                                        wmma::mem_row_major);
        }
        __syncwarp();

        // O = O*alpha + PV on owned half-row (registers)
#pragma unroll
        for (int c = 0; c < 32; c++)
            o_reg[c] = o_reg[c] * alpha + Ss[rown * LDF + c0 + c];
    }

    // Epilogue: normalize, write to [B,T,D]
    const int b = bh >> 4, h = bh & (NH - 1);
    const float inv = 1.0f / l_r;
    float* Og = O + ((size_t)(b * T_ + q0 + rown)) * DM + h * HD + c0;
#pragma unroll
    for (int c = 0; c < 32; c += 4) {
        float4 o = make_float4(o_reg[c] * inv, o_reg[c + 1] * inv,
                               o_reg[c + 2] * inv, o_reg[c + 3] * inv);
        *(float4*)&Og[c] = o;
    }
}

// ---------------------------------------------------------------------------
extern "C" void kernel_launch(void* const* d_in, const int* in_sizes, int n_in,
                              void* d_out, int out_size)
{
    (void)in_sizes; (void)n_in; (void)out_size;
    const float* x  = (const float*)d_in[0];
    const float* Wq = (const float*)d_in[1];
    const float* Wk = (const float*)d_in[2];
    const float* Wv = (const float*)d_in[3];
    const float* Wo = (const float*)d_in[4];
    const float* qw = (const float*)d_in[5];
    const float* kw = (const float*)d_in[6];
    float* out = (float*)d_out;

    float *qp, *kp, *vp, *ap;
    cudaGetSymbolAddress((void**)&qp, g_q);
    cudaGetSymbolAddress((void**)&kp, g_k);
    cudaGetSymbolAddress((void**)&vp, g_v);
    cudaGetSymbolAddress((void**)&ap, g_attn);

    const int GEMM_SMEM = GEMM_SMEM_FLOATS * 4;                 // 70656 B
    cudaFuncSetAttribute(qkv_gemm,
                         cudaFuncAttributeMaxDynamicSharedMemorySize, GEMM_SMEM);
    cudaFuncSetAttribute(oproj_gemm,
                         cudaFuncAttributeMaxDynamicSharedMemorySize, GEMM_SMEM);

    const int FLASH_SMEM = (2 * BR * LDF + 2 * BC * LDF) * 4;   // 104448 B
    cudaFuncSetAttribute(flash_kernel,
                         cudaFuncAttributeMaxDynamicSharedMemorySize, FLASH_SMEM);

    dim3 gq(DM / 128, ROWS / 128, 3);   // (8, 32, 3)
    qkv_gemm<<<gq, 256, GEMM_SMEM>>>(x, Wq, Wk, Wv, qp, kp, vp);

    rmsrope_kernel<<<B_ * NH * T_ / 8, 256>>>(qp, qw);
    rmsrope_kernel<<<B_ * NH * T_ / 8, 256>>>(kp, kw);

    flash_kernel<<<dim3(T_ / BR, B_ * NH), 256, FLASH_SMEM>>>(qp, kp, vp, ap);

    dim3 go(DM / 128, ROWS / 128);      // (8, 32)
    oproj_gemm<<<go, 256, GEMM_SMEM>>>(ap, Wo, out);
}

// round 6
// speedup vs baseline: 1.6549x; 1.5118x over previous
#include <cuda_runtime.h>
#include <mma.h>
#include <math.h>

using namespace nvcuda;

#define DM 1024
#define NH 16
#define HD 64
#define B_ 2
#define T_ 2048
#define ROWS (B_*T_)

#define BR 128
#define BC 64
#define LDQ 68
#define LDK 68
#define LDV 72

// Scratch (static device globals — allocation-free per harness rules)
__device__ float g_q[(size_t)B_*NH*T_*HD];     // [B,H,T,hd]
__device__ float g_k[(size_t)B_*NH*T_*HD];
__device__ float g_v[(size_t)B_*NH*T_*HD];
__device__ float g_attn[(size_t)ROWS*DM];      // [B,T,D]

__device__ __forceinline__ float ftf(float x) { return wmma::__float_to_tf32(x); }

__device__ __forceinline__ void cp_async16(void* smem_ptr, const void* gmem_ptr) {
    unsigned int saddr = (unsigned int)__cvta_generic_to_shared(smem_ptr);
    asm volatile("cp.async.cg.shared.global [%0], [%1], 16;\n"
                 :: "r"(saddr), "l"(gmem_ptr));
}
__device__ __forceinline__ void cp_commit() {
    asm volatile("cp.async.commit_group;\n");
}
__device__ __forceinline__ void cp_wait_all() {
    asm volatile("cp.async.wait_group 0;\n");
}

// mma.m16n8k8 tf32: D = A@B + D, A row-major 16x8, B col-major 8x8(kxn)
__device__ __forceinline__
void mma_tf32(float* c, unsigned a0, unsigned a1, unsigned a2, unsigned a3,
              unsigned b0, unsigned b1)
{
    asm volatile(
        "mma.sync.aligned.m16n8k8.row.col.f32.tf32.tf32.f32 "
        "{%0,%1,%2,%3},{%4,%5,%6,%7},{%8,%9},{%0,%1,%2,%3};\n"
        : "+f"(c[0]), "+f"(c[1]), "+f"(c[2]), "+f"(c[3])
        : "r"(a0), "r"(a1), "r"(a2), "r"(a3), "r"(b0), "r"(b1));
}

// ---------------------------------------------------------------------------
// tf32 wmma GEMM (round-2 proven version): C[M,N]=A[M,K]@B[K,N],
// 128x128 tile, BK=32, 8 warps x (64x32).
// ---------------------------------------------------------------------------
__device__ __forceinline__
void gemm_body(const float* __restrict__ A, const float* __restrict__ Bw,
               float* __restrict__ C, bool splitHeads)
{
    __shared__ float As[128][36];
    __shared__ float Bs[32][132];
    const int K = 1024, N = 1024;
    const int tid = threadIdx.x;
    const int wid = tid >> 5;
    const int warp_m = wid >> 2, warp_n = wid & 3;
    const int bm = blockIdx.y << 7, bn = blockIdx.x << 7;

    wmma::fragment<wmma::accumulator, 16, 16, 8, float> acc[4][2];
#pragma unroll
    for (int i = 0; i < 4; i++)
#pragma unroll
        for (int j = 0; j < 2; j++) wmma::fill_fragment(acc[i][j], 0.0f);

    for (int k0 = 0; k0 < K; k0 += 32) {
#pragma unroll
        for (int t = 0; t < 4; t++) {
            int f = tid + (t << 8);
            int ar = f >> 3, ac = (f & 7) << 2;
            float4 a4 = *(const float4*)&A[(size_t)(bm + ar) * K + k0 + ac];
            *(float4*)&As[ar][ac] = make_float4(ftf(a4.x), ftf(a4.y), ftf(a4.z), ftf(a4.w));
            int br = f >> 5, bc = (f & 31) << 2;
            float4 b4 = *(const float4*)&Bw[(size_t)(k0 + br) * N + bn + bc];
            *(float4*)&Bs[br][bc] = make_float4(ftf(b4.x), ftf(b4.y), ftf(b4.z), ftf(b4.w));
        }
        __syncthreads();
#pragma unroll
        for (int ks = 0; ks < 4; ks++) {
            wmma::fragment<wmma::matrix_a, 16, 16, 8, wmma::precision::tf32, wmma::row_major> af[4];
            wmma::fragment<wmma::matrix_b, 16, 16, 8, wmma::precision::tf32, wmma::row_major> bf[2];
#pragma unroll
            for (int i = 0; i < 4; i++)
                wmma::load_matrix_sync(af[i], &As[warp_m * 64 + i * 16][ks * 8], 36);
#pragma unroll
            for (int j = 0; j < 2; j++)
                wmma::load_matrix_sync(bf[j], &Bs[ks * 8][warp_n * 32 + j * 16], 132);
#pragma unroll
            for (int i = 0; i < 4; i++)
#pragma unroll
                for (int j = 0; j < 2; j++)
                    wmma::mma_sync(acc[i][j], af[i], bf[j], acc[i][j]);
        }
        __syncthreads();
    }

#pragma unroll
    for (int i = 0; i < 4; i++)
#pragma unroll
        for (int j = 0; j < 2; j++) {
            int m0 = bm + warp_m * 64 + i * 16;
            int n0 = bn + warp_n * 32 + j * 16;
            if (splitHeads) {
                int b = m0 >> 11, t = m0 & (T_ - 1);
                int h = n0 >> 6, d = n0 & (HD - 1);
                float* p = C + ((size_t)(b * NH + h) * T_ + t) * HD + d;
                wmma::store_matrix_sync(p, acc[i][j], HD, wmma::mem_row_major);
            } else {
                wmma::store_matrix_sync(C + (size_t)m0 * N + n0, acc[i][j], N,
                                        wmma::mem_row_major);
            }
        }
}

__global__ __launch_bounds__(256)
void qkv_gemm(const float* __restrict__ X,
              const float* __restrict__ Wq, const float* __restrict__ Wk,
              const float* __restrict__ Wv,
              float* __restrict__ Q, float* __restrict__ K, float* __restrict__ V)
{
    const float* W; float* C;
    if (blockIdx.z == 0)      { W = Wq; C = Q; }
    else if (blockIdx.z == 1) { W = Wk; C = K; }
    else                      { W = Wv; C = V; }
    gemm_body(X, W, C, true);
}

__global__ __launch_bounds__(256)
void oproj_gemm(const float* __restrict__ A, const float* __restrict__ W,
                float* __restrict__ C)
{
    gemm_body(A, W, C, false);
}

// ---------------------------------------------------------------------------
// Fused per-head RMSNorm + RoPE, in place on [B,H,T,hd]. One warp per row.
// ---------------------------------------------------------------------------
__global__ __launch_bounds__(256)
void rmsrope_kernel(float* __restrict__ X, const float* __restrict__ w)
{
    int row = blockIdx.x * 8 + (threadIdx.x >> 5);
    int lane = threadIdx.x & 31;
    float* p = X + (size_t)row * HD;
    float x1 = p[lane], x2 = p[lane + 32];
    float ss = x1 * x1 + x2 * x2;
#pragma unroll
    for (int off = 16; off; off >>= 1)
        ss += __shfl_xor_sync(0xffffffffu, ss, off);
    float rms = rsqrtf(ss * (1.0f / HD) + 1e-6f);
    float n1 = x1 * rms * w[lane];
    float n2 = x2 * rms * w[lane + 32];
    int t = row & (T_ - 1);
    float freq = (float)t * powf(10000.0f, -(float)(2 * lane) * (1.0f / HD));
    float sn, cs;
    sincosf(freq, &sn, &cs);
    p[lane]      = n1 * cs - n2 * sn;
    p[lane + 32] = n2 * cs + n1 * sn;
}

// ---------------------------------------------------------------------------
// Flash attention v2: raw mma.m16n8k8 tf32, fully register-resident
// S/softmax/P/O per warp strip (16 rows). Br=128 x Bc=64, 8 warps,
// cp.async double-buffered K/V, ONE __syncthreads per key tile.
//
// Fragment layouts (PTX ISA m16n8k8): g = lane>>2, t = lane&3.
//   A (16x8 row): a0=(g,t) a1=(g+8,t) a2=(g,t+4) a3=(g+8,t+4)
//   B (8x8 col):  b0=(k=t,n=g) b1=(k=t+4,n=g)
//   C (16x8):     c0=(g,2t) c1=(g,2t+1) c2=(g+8,2t) c3=(g+8,2t+1)
// ---------------------------------------------------------------------------
extern __shared__ float fsm[];
__global__ __launch_bounds__(256, 2)
void flash_kernel(const float* __restrict__ Q, const float* __restrict__ K,
                  const float* __restrict__ V, float* __restrict__ O)
{
    float* Qs = fsm;                              // [128][LDQ]
    float* Ks = Qs + BR * LDQ;                    // [2][64][LDK]
    float* Vs = Ks + 2 * BC * LDK;                // [2][64][LDV]

    const int tid  = threadIdx.x;
    const int wid  = tid >> 5;
    const int lane = tid & 31;
    const int g = lane >> 2, t = lane & 3;
    const int qt = gridDim.x - 1 - blockIdx.x;    // heavy tiles first
    const int q0 = qt << 7;
    const int bh = blockIdx.y;
    const float* Qg = Q + ((size_t)bh * T_ + q0) * HD;
    const float* Kg = K + (size_t)bh * T_ * HD;
    const float* Vg = V + (size_t)bh * T_ * HD;

    const int nkt = 2 * (qt + 1);

    // Prologue: issue K/V tile 0 via cp.async (raw fp32)
    {
        float* Kd = Ks; float* Vd = Vs;
#pragma unroll
        for (int p4 = 0; p4 < 4; p4++) {
            int f = tid + (p4 << 8);
            int r = f >> 4, c = (f & 15) << 2;
            cp_async16(&Kd[r * LDK + c], &Kg[(size_t)r * HD + c]);
            cp_async16(&Vd[r * LDV + c], &Vg[(size_t)r * HD + c]);
        }
        cp_commit();
    }

    // Load Q (scale 1/8 folded in — exact power of 2, then tf32 RN)
    for (int f = tid; f < BR * HD / 4; f += 256) {
        int r = f >> 4, c = (f & 15) << 2;
        float4 q4 = *(const float4*)&Qg[(size_t)r * HD + c];
        *(float4*)&Qs[r * LDQ + c] =
            make_float4(ftf(q4.x * 0.125f), ftf(q4.y * 0.125f),
                        ftf(q4.z * 0.125f), ftf(q4.w * 0.125f));
    }

    float m0 = -1e30f, m1 = -1e30f, l0 = 0.f, l1 = 0.f;
    float o[8][4];
#pragma unroll
    for (int j = 0; j < 8; j++)
#pragma unroll
        for (int e = 0; e < 4; e++) o[j][e] = 0.f;

    const int qi0 = q0 + wid * 16 + g;      // global row of c0/c1
    const int qrow_base = wid * 16 + g;

    for (int kt = 0; kt < nkt; kt++) {
        const int k0 = kt << 6;
        const int s = kt & 1;
        float* Kd = Ks + s * BC * LDK;
        float* Vd = Vs + s * BC * LDV;

        cp_wait_all();
        __syncthreads();    // tile kt visible to all; all warps done with buf s^1

        if (kt + 1 < nkt) { // prefetch next tile into the other buffer
            const int kn = (kt + 1) << 6;
            float* Kn = Ks + (s ^ 1) * BC * LDK;
            float* Vn = Vs + (s ^ 1) * BC * LDV;
#pragma unroll
            for (int p4 = 0; p4 < 4; p4++) {
                int f = tid + (p4 << 8);
                int r = f >> 4, c = (f & 15) << 2;
                cp_async16(&Kn[r * LDK + c], &Kg[(size_t)(kn + r) * HD + c]);
                cp_async16(&Vn[r * LDV + c], &Vg[(size_t)(kn + r) * HD + c]);
            }
            cp_commit();
        }

        // ---- S = Q @ K^T : 8 n8-tiles, k-loop over d ----
        float sc[8][4];
#pragma unroll
        for (int j = 0; j < 8; j++)
#pragma unroll
            for (int e = 0; e < 4; e++) sc[j][e] = 0.f;

#pragma unroll
        for (int d0 = 0; d0 < HD; d0 += 8) {
            const float* qrow0 = &Qs[(wid * 16 + g) * LDQ + d0];
            unsigned a0 = __float_as_uint(qrow0[t]);
            unsigned a1 = __float_as_uint(qrow0[8 * LDQ + t]);
            unsigned a2 = __float_as_uint(qrow0[t + 4]);
            unsigned a3 = __float_as_uint(qrow0[8 * LDQ + t + 4]);
#pragma unroll
            for (int j = 0; j < 8; j++) {
                const float* krow = &Kd[(8 * j + g) * LDK + d0];
                unsigned b0 = __float_as_uint(ftf(krow[t]));
                unsigned b1 = __float_as_uint(ftf(krow[t + 4]));
                mma_tf32(sc[j], a0, a1, a2, a3, b0, b1);
            }
        }

        // ---- mask (only possibly-diagonal tiles) + online softmax ----
        if (kt >= nkt - 2) {
#pragma unroll
            for (int j = 0; j < 8; j++) {
                int ki = k0 + 8 * j + 2 * t;
                if (ki     > qi0)     sc[j][0] = -1e30f;
                if (ki + 1 > qi0)     sc[j][1] = -1e30f;
                if (ki     > qi0 + 8) sc[j][2] = -1e30f;
                if (ki + 1 > qi0 + 8) sc[j][3] = -1e30f;
            }
        }

        float mx0 = -1e30f, mx1 = -1e30f;
#pragma unroll
        for (int j = 0; j < 8; j++) {
            mx0 = fmaxf(mx0, fmaxf(sc[j][0], sc[j][1]));
            mx1 = fmaxf(mx1, fmaxf(sc[j][2], sc[j][3]));
        }
        mx0 = fmaxf(mx0, __shfl_xor_sync(0xffffffffu, mx0, 1));
        mx0 = fmaxf(mx0, __shfl_xor_sync(0xffffffffu, mx0, 2));
        mx1 = fmaxf(mx1, __shfl_xor_sync(0xffffffffu, mx1, 1));
        mx1 = fmaxf(mx1, __shfl_xor_sync(0xffffffffu, mx1, 2));

        float nm0 = fmaxf(m0, mx0), nm1 = fmaxf(m1, mx1);
        float al0 = __expf(m0 - nm0), al1 = __expf(m1 - nm1);
        m0 = nm0; m1 = nm1;

        float sum0 = 0.f, sum1 = 0.f;
#pragma unroll
        for (int j = 0; j < 8; j++) {
            float p0 = __expf(sc[j][0] - nm0);
            float p1 = __expf(sc[j][1] - nm0);
            float p2 = __expf(sc[j][2] - nm1);
            float p3 = __expf(sc[j][3] - nm1);
            sum0 += p0 + p1; sum1 += p2 + p3;
            sc[j][0] = ftf(p0); sc[j][1] = ftf(p1);
            sc[j][2] = ftf(p2); sc[j][3] = ftf(p3);
        }
        sum0 += __shfl_xor_sync(0xffffffffu, sum0, 1);
        sum0 += __shfl_xor_sync(0xffffffffu, sum0, 2);
        sum1 += __shfl_xor_sync(0xffffffffu, sum1, 1);
        sum1 += __shfl_xor_sync(0xffffffffu, sum1, 2);
        l0 = l0 * al0 + sum0;
        l1 = l1 * al1 + sum1;

#pragma unroll
        for (int j = 0; j < 8; j++) {
            o[j][0] *= al0; o[j][1] *= al0;
            o[j][2] *= al1; o[j][3] *= al1;
        }

        // ---- PV: O += P @ V ----
        const int src0 = (lane & ~3) | (t >> 1);
        const int src2 = src0 | 2;
        const bool odd = (lane & 1);
#pragma unroll
        for (int ks = 0; ks < 8; ks++) {
            // C-layout P -> A-layout fragment via 4-lane exchange
            float v00 = __shfl_sync(0xffffffffu, sc[ks][0], src0);
            float v01 = __shfl_sync(0xffffffffu, sc[ks][1], src0);
            float v10 = __shfl_sync(0xffffffffu, sc[ks][2], src0);
            float v11 = __shfl_sync(0xffffffffu, sc[ks][3], src0);
            float v20 = __shfl_sync(0xffffffffu, sc[ks][0], src2);
            float v21 = __shfl_sync(0xffffffffu, sc[ks][1], src2);
            float v30 = __shfl_sync(0xffffffffu, sc[ks][2], src2);
            float v31 = __shfl_sync(0xffffffffu, sc[ks][3], src2);
            unsigned a0 = __float_as_uint(odd ? v01 : v00);
            unsigned a1 = __float_as_uint(odd ? v11 : v10);
            unsigned a2 = __float_as_uint(odd ? v21 : v20);
            unsigned a3 = __float_as_uint(odd ? v31 : v30);
#pragma unroll
            for (int jd = 0; jd < 8; jd++) {
                unsigned b0 = __float_as_uint(ftf(Vd[(8 * ks + t) * LDV + 8 * jd + g]));
                unsigned b1 = __float_as_uint(ftf(Vd[(8 * ks + t + 4) * LDV + 8 * jd + g]));
                mma_tf32(o[jd], a0, a1, a2, a3, b0, b1);
            }
        }
    }

    // Epilogue: normalize, write to [B,T,D]
    const int b = bh >> 4, h = bh & (NH - 1);
    const float inv0 = 1.0f / l0, inv1 = 1.0f / l1;
    float* Og0 = O + ((size_t)(b * T_ + q0 + qrow_base)) * DM + h * HD;
    float* Og1 = Og0 + (size_t)8 * DM;
#pragma unroll
    for (int jd = 0; jd < 8; jd++) {
        int col = 8 * jd + 2 * t;
        *(float2*)&Og0[col] = make_float2(o[jd][0] * inv0, o[jd][1] * inv0);
        *(float2*)&Og1[col] = make_float2(o[jd][2] * inv1, o[jd][3] * inv1);
    }
}

// ---------------------------------------------------------------------------
extern "C" void kernel_launch(void* const* d_in, const int* in_sizes, int n_in,
                              void* d_out, int out_size)
{
    (void)in_sizes; (void)n_in; (void)out_size;
    const float* x  = (const float*)d_in[0];
    const float* Wq = (const float*)d_in[1];
    const float* Wk = (const float*)d_in[2];
    const float* Wv = (const float*)d_in[3];
    const float* Wo = (const float*)d_in[4];
    const float* qw = (const float*)d_in[5];
    const float* kw = (const float*)d_in[6];
    float* out = (float*)d_out;

    float *qp, *kp, *vp, *ap;
    cudaGetSymbolAddress((void**)&qp, g_q);
    cudaGetSymbolAddress((void**)&kp, g_k);
    cudaGetSymbolAddress((void**)&vp, g_v);
    cudaGetSymbolAddress((void**)&ap, g_attn);

    const int FLASH_SMEM = (BR * LDQ + 2 * BC * LDK + 2 * BC * LDV) * 4;  // 106496
    cudaFuncSetAttribute(flash_kernel,
                         cudaFuncAttributeMaxDynamicSharedMemorySize, FLASH_SMEM);

    dim3 gq(DM / 128, ROWS / 128, 3);   // (8, 32, 3)
    qkv_gemm<<<gq, 256>>>(x, Wq, Wk, Wv, qp, kp, vp);

    rmsrope_kernel<<<B_ * NH * T_ / 8, 256>>>(qp, qw);
    rmsrope_kernel<<<B_ * NH * T_ / 8, 256>>>(kp, kw);

    flash_kernel<<<dim3(T_ / BR, B_ * NH), 256, FLASH_SMEM>>>(qp, kp, vp, ap);

    dim3 go(DM / 128, ROWS / 128);      // (8, 32)
    oproj_gemm<<<go, 256>>>(ap, Wo, out);
}

// round 7
// speedup vs baseline: 2.3529x; 1.4218x over previous
#include <cuda_runtime.h>
#include <mma.h>
#include <math.h>

using namespace nvcuda;

#define DM 1024
#define NH 16
#define HD 64
#define B_ 2
#define T_ 2048
#define ROWS (B_*T_)

#define BR 128
#define BC 64
#define LDQ 68
#define LDK 68
#define LDV 72

// GEMM pipeline geometry
#define GBK 16
#define LDA 20              // As row pitch (floats)  -> lane addr 20g+t covers 0..31
#define LDB 136             // Bs row pitch (floats)  -> lane addr 8t+g distinct
#define AS_STAGE (128*LDA)  // 2560 floats
#define BS_STAGE (GBK*LDB)  // 2176 floats
#define GEMM_NIT (1024/GBK) // 64
#define GEMM_SMEM ((3*(AS_STAGE+BS_STAGE))*4)   // 56832 B

// Scratch (static device globals — allocation-free per harness rules)
__device__ float g_q[(size_t)B_*NH*T_*HD];     // [B,H,T,hd]
__device__ float g_k[(size_t)B_*NH*T_*HD];
__device__ float g_v[(size_t)B_*NH*T_*HD];
__device__ float g_attn[(size_t)ROWS*DM];      // [B,T,D]

__device__ __forceinline__ float ftf(float x) { return wmma::__float_to_tf32(x); }

__device__ __forceinline__ void cp_async16(void* smem_ptr, const void* gmem_ptr) {
    unsigned int saddr = (unsigned int)__cvta_generic_to_shared(smem_ptr);
    asm volatile("cp.async.cg.shared.global [%0], [%1], 16;\n"
                 :: "r"(saddr), "l"(gmem_ptr));
}
__device__ __forceinline__ void cp_commit() {
    asm volatile("cp.async.commit_group;\n");
}
template<int N>
__device__ __forceinline__ void cp_wait() {
    asm volatile("cp.async.wait_group %0;\n" :: "n"(N));
}

// mma.m16n8k8 tf32: D = A@B + D, A row-major 16x8, B col-major 8x8(kxn)
// Layouts: g=lane>>2, t=lane&3.
//   A: a0=(g,t) a1=(g+8,t) a2=(g,t+4) a3=(g+8,t+4)
//   B: b0=(k=t,n=g) b1=(k=t+4,n=g)
//   C: c0=(g,2t) c1=(g,2t+1) c2=(g+8,2t) c3=(g+8,2t+1)
__device__ __forceinline__
void mma_tf32(float* c, unsigned a0, unsigned a1, unsigned a2, unsigned a3,
              unsigned b0, unsigned b1)
{
    asm volatile(
        "mma.sync.aligned.m16n8k8.row.col.f32.tf32.tf32.f32 "
        "{%0,%1,%2,%3},{%4,%5,%6,%7},{%8,%9},{%0,%1,%2,%3};\n"
        : "+f"(c[0]), "+f"(c[1]), "+f"(c[2]), "+f"(c[3])
        : "r"(a0), "r"(a1), "r"(a2), "r"(a3), "r"(b0), "r"(b1));
}

// ---------------------------------------------------------------------------
// tf32 raw-mma GEMM: C[M,N]=A[M,K]@B[K,N], K=N=1024. 128x128 tile, BK=16,
// 3-stage cp.async pipeline, one __syncthreads per K-slab.
// 8 warps (2x4), warp tile 64x32 = 4x4 m16n8k8 accumulators.
// ---------------------------------------------------------------------------
extern __shared__ float gsm[];

__device__ __forceinline__
void gemm_issue(const float* __restrict__ A, const float* __restrict__ Bw,
                float* As, float* Bs, int bm, int bn, int k0, int tid)
{
#pragma unroll
    for (int p = 0; p < 2; p++) {
        int f = tid + (p << 8);
        int ar = f >> 2, ac = (f & 3) << 2;        // A: 128 rows x 16 cols
        cp_async16(&As[ar * LDA + ac], &A[(size_t)(bm + ar) * 1024 + k0 + ac]);
        int br = f >> 5, bc = (f & 31) << 2;       // B: 16 rows x 128 cols
        cp_async16(&Bs[br * LDB + bc], &Bw[(size_t)(k0 + br) * 1024 + bn + bc]);
    }
    cp_commit();
}

__device__ __forceinline__
void gemm_compute(const float* As, const float* Bs, float acc[4][4][4],
                  int wm, int wn, int g, int t)
{
#pragma unroll
    for (int ks = 0; ks < 2; ks++) {
        unsigned a[4][4], b[4][2];
#pragma unroll
        for (int i = 0; i < 4; i++) {
            const float* ap = As + (wm * 64 + i * 16 + g) * LDA + ks * 8;
            a[i][0] = __float_as_uint(ftf(ap[t]));
            a[i][1] = __float_as_uint(ftf(ap[8 * LDA + t]));
            a[i][2] = __float_as_uint(ftf(ap[t + 4]));
            a[i][3] = __float_as_uint(ftf(ap[8 * LDA + t + 4]));
        }
#pragma unroll
        for (int j = 0; j < 4; j++) {
            const float* bp = Bs + (ks * 8) * LDB + wn * 32 + j * 8 + g;
            b[j][0] = __float_as_uint(ftf(bp[t * LDB]));
            b[j][1] = __float_as_uint(ftf(bp[(t + 4) * LDB]));
        }
#pragma unroll
        for (int i = 0; i < 4; i++)
#pragma unroll
            for (int j = 0; j < 4; j++)
                mma_tf32(acc[i][j], a[i][0], a[i][1], a[i][2], a[i][3],
                         b[j][0], b[j][1]);
    }
}

__device__ __forceinline__
void gemm_body(const float* __restrict__ A, const float* __restrict__ Bw,
               float* __restrict__ C, bool splitHeads)
{
    float* As = gsm;                         // [3][128][LDA]
    float* Bs = gsm + 3 * AS_STAGE;          // [3][16][LDB]
    const int tid  = threadIdx.x;
    const int wid  = tid >> 5;
    const int lane = tid & 31;
    const int g = lane >> 2, t = lane & 3;
    const int wm = wid >> 2, wn = wid & 3;
    const int bm = blockIdx.y << 7, bn = blockIdx.x << 7;

    float acc[4][4][4];
#pragma unroll
    for (int i = 0; i < 4; i++)
#pragma unroll
        for (int j = 0; j < 4; j++)
#pragma unroll
            for (int e = 0; e < 4; e++) acc[i][j][e] = 0.f;

    gemm_issue(A, Bw, As, Bs, bm, bn, 0, tid);
    gemm_issue(A, Bw, As + AS_STAGE, Bs + BS_STAGE, bm, bn, GBK, tid);

    for (int it = 0; it < GEMM_NIT - 1; it++) {
        cp_wait<1>();
        __syncthreads();
        if (it + 2 < GEMM_NIT) {
            int sb = (it + 2) % 3;
            gemm_issue(A, Bw, As + sb * AS_STAGE, Bs + sb * BS_STAGE,
                       bm, bn, (it + 2) * GBK, tid);
        }
        int s = it % 3;
        gemm_compute(As + s * AS_STAGE, Bs + s * BS_STAGE, acc, wm, wn, g, t);
    }
    cp_wait<0>();
    __syncthreads();
    {
        int s = (GEMM_NIT - 1) % 3;
        gemm_compute(As + s * AS_STAGE, Bs + s * BS_STAGE, acc, wm, wn, g, t);
    }

    // Epilogue: fragment float2 stores straight to gmem
#pragma unroll
    for (int i = 0; i < 4; i++) {
        int m0 = bm + wm * 64 + i * 16;
#pragma unroll
        for (int j = 0; j < 4; j++) {
            int col = bn + wn * 32 + j * 8 + 2 * t;
            int r0 = m0 + g, r1 = m0 + 8 + g;
            if (splitHeads) {
                int h = (col >> 6) & (NH - 1), d = col & (HD - 1);
                int b0r = r0 >> 11, t0 = r0 & (T_ - 1);
                int b1r = r1 >> 11, t1 = r1 & (T_ - 1);
                *(float2*)&C[((size_t)(b0r * NH + h) * T_ + t0) * HD + d] =
                    make_float2(acc[i][j][0], acc[i][j][1]);
                *(float2*)&C[((size_t)(b1r * NH + h) * T_ + t1) * HD + d] =
                    make_float2(acc[i][j][2], acc[i][j][3]);
            } else {
                *(float2*)&C[(size_t)r0 * DM + col] =
                    make_float2(acc[i][j][0], acc[i][j][1]);
                *(float2*)&C[(size_t)r1 * DM + col] =
                    make_float2(acc[i][j][2], acc[i][j][3]);
            }
        }
    }
}

__global__ __launch_bounds__(256, 2)
void qkv_gemm(const float* __restrict__ X,
              const float* __restrict__ Wq, const float* __restrict__ Wk,
              const float* __restrict__ Wv,
              float* __restrict__ Q, float* __restrict__ K, float* __restrict__ V)
{
    const float* W; float* C;
    if (blockIdx.z == 0)      { W = Wq; C = Q; }
    else if (blockIdx.z == 1) { W = Wk; C = K; }
    else                      { W = Wv; C = V; }
    gemm_body(X, W, C, true);
}

__global__ __launch_bounds__(256, 2)
void oproj_gemm(const float* __restrict__ A, const float* __restrict__ W,
                float* __restrict__ C)
{
    gemm_body(A, W, C, false);
}

// ---------------------------------------------------------------------------
// Fused per-head RMSNorm + RoPE, in place on [B,H,T,hd]. One warp per row.
// ---------------------------------------------------------------------------
__global__ __launch_bounds__(256)
void rmsrope_kernel(float* __restrict__ X, const float* __restrict__ w)
{
    int row = blockIdx.x * 8 + (threadIdx.x >> 5);
    int lane = threadIdx.x & 31;
    float* p = X + (size_t)row * HD;
    float x1 = p[lane], x2 = p[lane + 32];
    float ss = x1 * x1 + x2 * x2;
#pragma unroll
    for (int off = 16; off; off >>= 1)
        ss += __shfl_xor_sync(0xffffffffu, ss, off);
    float rms = rsqrtf(ss * (1.0f / HD) + 1e-6f);
    float n1 = x1 * rms * w[lane];
    float n2 = x2 * rms * w[lane + 32];
    int t = row & (T_ - 1);
    float freq = (float)t * powf(10000.0f, -(float)(2 * lane) * (1.0f / HD));
    float sn, cs;
    sincosf(freq, &sn, &cs);
    p[lane]      = n1 * cs - n2 * sn;
    p[lane + 32] = n2 * cs + n1 * sn;
}

// ---------------------------------------------------------------------------
// Flash attention v2 (round-6 proven): raw mma.m16n8k8 tf32, register-resident
// S/softmax/P/O per warp strip. Br=128 x Bc=64, 8 warps, cp.async
// double-buffered K/V, one __syncthreads per key tile.
// ---------------------------------------------------------------------------
extern __shared__ float fsm[];
__global__ __launch_bounds__(256, 2)
void flash_kernel(const float* __restrict__ Q, const float* __restrict__ K,
                  const float* __restrict__ V, float* __restrict__ O)
{
    float* Qs = fsm;                              // [128][LDQ]
    float* Ks = Qs + BR * LDQ;                    // [2][64][LDK]
    float* Vs = Ks + 2 * BC * LDK;                // [2][64][LDV]

    const int tid  = threadIdx.x;
    const int wid  = tid >> 5;
    const int lane = tid & 31;
    const int g = lane >> 2, t = lane & 3;
    const int qt = gridDim.x - 1 - blockIdx.x;    // heavy tiles first
    const int q0 = qt << 7;
    const int bh = blockIdx.y;
    const float* Qg = Q + ((size_t)bh * T_ + q0) * HD;
    const float* Kg = K + (size_t)bh * T_ * HD;
    const float* Vg = V + (size_t)bh * T_ * HD;

    const int nkt = 2 * (qt + 1);

    // Prologue: issue K/V tile 0 via cp.async (raw fp32)
    {
        float* Kd = Ks; float* Vd = Vs;
#pragma unroll
        for (int p4 = 0; p4 < 4; p4++) {
            int f = tid + (p4 << 8);
            int r = f >> 4, c = (f & 15) << 2;
            cp_async16(&Kd[r * LDK + c], &Kg[(size_t)r * HD + c]);
            cp_async16(&Vd[r * LDV + c], &Vg[(size_t)r * HD + c]);
        }
        cp_commit();
    }

    // Load Q (scale 1/8 folded in — exact power of 2, then tf32 RN)
    for (int f = tid; f < BR * HD / 4; f += 256) {
        int r = f >> 4, c = (f & 15) << 2;
        float4 q4 = *(const float4*)&Qg[(size_t)r * HD + c];
        *(float4*)&Qs[r * LDQ + c] =
            make_float4(ftf(q4.x * 0.125f), ftf(q4.y * 0.125f),
                        ftf(q4.z * 0.125f), ftf(q4.w * 0.125f));
    }

    float m0 = -1e30f, m1 = -1e30f, l0 = 0.f, l1 = 0.f;
    float o[8][4];
#pragma unroll
    for (int j = 0; j < 8; j++)
#pragma unroll
        for (int e = 0; e < 4; e++) o[j][e] = 0.f;

    const int qi0 = q0 + wid * 16 + g;
    const int qrow_base = wid * 16 + g;

    for (int kt = 0; kt < nkt; kt++) {
        const int k0 = kt << 6;
        const int s = kt & 1;
        float* Kd = Ks + s * BC * LDK;
        float* Vd = Vs + s * BC * LDV;

        cp_wait<0>();
        __syncthreads();

        if (kt + 1 < nkt) {
            const int kn = (kt + 1) << 6;
            float* Kn = Ks + (s ^ 1) * BC * LDK;
            float* Vn = Vs + (s ^ 1) * BC * LDV;
#pragma unroll
            for (int p4 = 0; p4 < 4; p4++) {
                int f = tid + (p4 << 8);
                int r = f >> 4, c = (f & 15) << 2;
                cp_async16(&Kn[r * LDK + c], &Kg[(size_t)(kn + r) * HD + c]);
                cp_async16(&Vn[r * LDV + c], &Vg[(size_t)(kn + r) * HD + c]);
            }
            cp_commit();
        }

        // ---- S = Q @ K^T ----
        float sc[8][4];
#pragma unroll
        for (int j = 0; j < 8; j++)
#pragma unroll
            for (int e = 0; e < 4; e++) sc[j][e] = 0.f;

#pragma unroll
        for (int d0 = 0; d0 < HD; d0 += 8) {
            const float* qrow0 = &Qs[(wid * 16 + g) * LDQ + d0];
            unsigned a0 = __float_as_uint(qrow0[t]);
            unsigned a1 = __float_as_uint(qrow0[8 * LDQ + t]);
            unsigned a2 = __float_as_uint(qrow0[t + 4]);
            unsigned a3 = __float_as_uint(qrow0[8 * LDQ + t + 4]);
#pragma unroll
            for (int j = 0; j < 8; j++) {
                const float* krow = &Kd[(8 * j + g) * LDK + d0];
                unsigned b0 = __float_as_uint(ftf(krow[t]));
                unsigned b1 = __float_as_uint(ftf(krow[t + 4]));
                mma_tf32(sc[j], a0, a1, a2, a3, b0, b1);
            }
        }

        // ---- mask + online softmax (registers) ----
        if (kt >= nkt - 2) {
#pragma unroll
            for (int j = 0; j < 8; j++) {
                int ki = k0 + 8 * j + 2 * t;
                if (ki     > qi0)     sc[j][0] = -1e30f;
                if (ki + 1 > qi0)     sc[j][1] = -1e30f;
                if (ki     > qi0 + 8) sc[j][2] = -1e30f;
                if (ki + 1 > qi0 + 8) sc[j][3] = -1e30f;
            }
        }

        float mx0 = -1e30f, mx1 = -1e30f;
#pragma unroll
        for (int j = 0; j < 8; j++) {
            mx0 = fmaxf(mx0, fmaxf(sc[j][0], sc[j][1]));
            mx1 = fmaxf(mx1, fmaxf(sc[j][2], sc[j][3]));
        }
        mx0 = fmaxf(mx0, __shfl_xor_sync(0xffffffffu, mx0, 1));
        mx0 = fmaxf(mx0, __shfl_xor_sync(0xffffffffu, mx0, 2));
        mx1 = fmaxf(mx1, __shfl_xor_sync(0xffffffffu, mx1, 1));
        mx1 = fmaxf(mx1, __shfl_xor_sync(0xffffffffu, mx1, 2));

        float nm0 = fmaxf(m0, mx0), nm1 = fmaxf(m1, mx1);
        float al0 = __expf(m0 - nm0), al1 = __expf(m1 - nm1);
        m0 = nm0; m1 = nm1;

        float sum0 = 0.f, sum1 = 0.f;
#pragma unroll
        for (int j = 0; j < 8; j++) {
            float p0 = __expf(sc[j][0] - nm0);
            float p1 = __expf(sc[j][1] - nm0);
            float p2 = __expf(sc[j][2] - nm1);
            float p3 = __expf(sc[j][3] - nm1);
            sum0 += p0 + p1; sum1 += p2 + p3;
            sc[j][0] = ftf(p0); sc[j][1] = ftf(p1);
            sc[j][2] = ftf(p2); sc[j][3] = ftf(p3);
        }
        sum0 += __shfl_xor_sync(0xffffffffu, sum0, 1);
        sum0 += __shfl_xor_sync(0xffffffffu, sum0, 2);
        sum1 += __shfl_xor_sync(0xffffffffu, sum1, 1);
        sum1 += __shfl_xor_sync(0xffffffffu, sum1, 2);
        l0 = l0 * al0 + sum0;
        l1 = l1 * al1 + sum1;

#pragma unroll
        for (int j = 0; j < 8; j++) {
            o[j][0] *= al0; o[j][1] *= al0;
            o[j][2] *= al1; o[j][3] *= al1;
        }

        // ---- PV: O += P @ V ----
        const int src0 = (lane & ~3) | (t >> 1);
        const int src2 = src0 | 2;
        const bool odd = (lane & 1);
#pragma unroll
        for (int ks = 0; ks < 8; ks++) {
            float v00 = __shfl_sync(0xffffffffu, sc[ks][0], src0);
            float v01 = __shfl_sync(0xffffffffu, sc[ks][1], src0);
            float v10 = __shfl_sync(0xffffffffu, sc[ks][2], src0);
            float v11 = __shfl_sync(0xffffffffu, sc[ks][3], src0);
            float v20 = __shfl_sync(0xffffffffu, sc[ks][0], src2);
            float v21 = __shfl_sync(0xffffffffu, sc[ks][1], src2);
            float v30 = __shfl_sync(0xffffffffu, sc[ks][2], src2);
            float v31 = __shfl_sync(0xffffffffu, sc[ks][3], src2);
            unsigned a0 = __float_as_uint(odd ? v01 : v00);
            unsigned a1 = __float_as_uint(odd ? v11 : v10);
            unsigned a2 = __float_as_uint(odd ? v21 : v20);
            unsigned a3 = __float_as_uint(odd ? v31 : v30);
#pragma unroll
            for (int jd = 0; jd < 8; jd++) {
                unsigned b0 = __float_as_uint(ftf(Vd[(8 * ks + t) * LDV + 8 * jd + g]));
                unsigned b1 = __float_as_uint(ftf(Vd[(8 * ks + t + 4) * LDV + 8 * jd + g]));
                mma_tf32(o[jd], a0, a1, a2, a3, b0, b1);
            }
        }
    }

    // Epilogue: normalize, write to [B,T,D]
    const int b = bh >> 4, h = bh & (NH - 1);
    const float inv0 = 1.0f / l0, inv1 = 1.0f / l1;
    float* Og0 = O + ((size_t)(b * T_ + q0 + qrow_base)) * DM + h * HD;
    float* Og1 = Og0 + (size_t)8 * DM;
#pragma unroll
    for (int jd = 0; jd < 8; jd++) {
        int col = 8 * jd + 2 * t;
        *(float2*)&Og0[col] = make_float2(o[jd][0] * inv0, o[jd][1] * inv0);
        *(float2*)&Og1[col] = make_float2(o[jd][2] * inv1, o[jd][3] * inv1);
    }
}

// ---------------------------------------------------------------------------
extern "C" void kernel_launch(void* const* d_in, const int* in_sizes, int n_in,
                              void* d_out, int out_size)
{
    (void)in_sizes; (void)n_in; (void)out_size;
    const float* x  = (const float*)d_in[0];
    const float* Wq = (const float*)d_in[1];
    const float* Wk = (const float*)d_in[2];
    const float* Wv = (const float*)d_in[3];
    const float* Wo = (const float*)d_in[4];
    const float* qw = (const float*)d_in[5];
    const float* kw = (const float*)d_in[6];
    float* out = (float*)d_out;

    float *qp, *kp, *vp, *ap;
    cudaGetSymbolAddress((void**)&qp, g_q);
    cudaGetSymbolAddress((void**)&kp, g_k);
    cudaGetSymbolAddress((void**)&vp, g_v);
    cudaGetSymbolAddress((void**)&ap, g_attn);

    cudaFuncSetAttribute(qkv_gemm,
                         cudaFuncAttributeMaxDynamicSharedMemorySize, GEMM_SMEM);
    cudaFuncSetAttribute(oproj_gemm,
                         cudaFuncAttributeMaxDynamicSharedMemorySize, GEMM_SMEM);

    const int FLASH_SMEM = (BR * LDQ + 2 * BC * LDK + 2 * BC * LDV) * 4;  // 106496
    cudaFuncSetAttribute(flash_kernel,
                         cudaFuncAttributeMaxDynamicSharedMemorySize, FLASH_SMEM);

    dim3 gq(DM / 128, ROWS / 128, 3);   // (8, 32, 3)
    qkv_gemm<<<gq, 256, GEMM_SMEM>>>(x, Wq, Wk, Wv, qp, kp, vp);

    rmsrope_kernel<<<B_ * NH * T_ / 8, 256>>>(qp, qw);
    rmsrope_kernel<<<B_ * NH * T_ / 8, 256>>>(kp, kw);

    flash_kernel<<<dim3(T_ / BR, B_ * NH), 256, FLASH_SMEM>>>(qp, kp, vp, ap);

    dim3 go(DM / 128, ROWS / 128);      // (8, 32)
    oproj_gemm<<<go, 256, GEMM_SMEM>>>(ap, Wo, out);
}

// round 8
// speedup vs baseline: 2.4615x; 1.0462x over previous
#include <cuda_runtime.h>
#include <mma.h>
#include <math.h>

using namespace nvcuda;

#define DM 1024
#define NH 16
#define HD 64
#define B_ 2
#define T_ 2048
#define ROWS (B_*T_)

#define BR 128
#define BC 64
#define LDQ 68
#define LDK 68
#define LDV 72

// GEMM pipeline geometry (BK=32, 3 stages)
#define GBK 32
#define LDA 36              // As row pitch -> a-frag banks 4g+t, conflict-free
#define LDB 136             // Bs row pitch -> b-frag banks 8t+g, conflict-free
#define AS_STAGE (128*LDA)  // 4608 floats
#define BS_STAGE (GBK*LDB)  // 4352 floats
#define GEMM_NIT (1024/GBK) // 32
#define GEMM_SMEM ((3*(AS_STAGE+BS_STAGE))*4)   // 107520 B

// Scratch (static device globals — allocation-free per harness rules)
__device__ float g_q[(size_t)B_*NH*T_*HD];     // [B,H,T,hd]
__device__ float g_k[(size_t)B_*NH*T_*HD];
__device__ float g_v[(size_t)B_*NH*T_*HD];
__device__ float g_attn[(size_t)ROWS*DM];      // [B,T,D]

__device__ __forceinline__ float ftf(float x) { return wmma::__float_to_tf32(x); }

__device__ __forceinline__ void cp_async16(void* smem_ptr, const void* gmem_ptr) {
    unsigned int saddr = (unsigned int)__cvta_generic_to_shared(smem_ptr);
    asm volatile("cp.async.cg.shared.global [%0], [%1], 16;\n"
                 :: "r"(saddr), "l"(gmem_ptr));
}
__device__ __forceinline__ void cp_commit() {
    asm volatile("cp.async.commit_group;\n");
}
template<int N>
__device__ __forceinline__ void cp_wait() {
    asm volatile("cp.async.wait_group %0;\n" :: "n"(N));
}

// mma.m16n8k8 tf32: D = A@B + D. g=lane>>2, t=lane&3.
//   A: a0=(g,t) a1=(g+8,t) a2=(g,t+4) a3=(g+8,t+4)
//   B: b0=(k=t,n=g) b1=(k=t+4,n=g)
//   C: c0=(g,2t) c1=(g,2t+1) c2=(g+8,2t) c3=(g+8,2t+1)
__device__ __forceinline__
void mma_tf32(float* c, unsigned a0, unsigned a1, unsigned a2, unsigned a3,
              unsigned b0, unsigned b1)
{
    asm volatile(
        "mma.sync.aligned.m16n8k8.row.col.f32.tf32.tf32.f32 "
        "{%0,%1,%2,%3},{%4,%5,%6,%7},{%8,%9},{%0,%1,%2,%3};\n"
        : "+f"(c[0]), "+f"(c[1]), "+f"(c[2]), "+f"(c[3])
        : "r"(a0), "r"(a1), "r"(a2), "r"(a3), "r"(b0), "r"(b1));
}

// ---------------------------------------------------------------------------
// tf32 raw-mma GEMM: C[M,N]=A[M,K]@B[K,N], K=N=1024. 128x128 tile, BK=32,
// 3-stage cp.async pipeline, one __syncthreads per K-slab (32 slabs).
// 8 warps (2x4), warp tile 64x32 = 4x4 m16n8k8 accumulators.
// ---------------------------------------------------------------------------
extern __shared__ float gsm[];

__device__ __forceinline__
void gemm_issue(const float* __restrict__ A, const float* __restrict__ Bw,
                float* As, float* Bs, int bm, int bn, int k0, int tid)
{
#pragma unroll
    for (int p = 0; p < 4; p++) {
        int f = tid + (p << 8);
        int ar = f >> 3, ac = (f & 7) << 2;        // A: 128 rows x 32 cols
        cp_async16(&As[ar * LDA + ac], &A[(size_t)(bm + ar) * 1024 + k0 + ac]);
        int br = f >> 5, bc = (f & 31) << 2;       // B: 32 rows x 128 cols
        cp_async16(&Bs[br * LDB + bc], &Bw[(size_t)(k0 + br) * 1024 + bn + bc]);
    }
    cp_commit();
}

__device__ __forceinline__
void gemm_compute(const float* As, const float* Bs, float acc[4][4][4],
                  int wm, int wn, int g, int t)
{
#pragma unroll
    for (int ks = 0; ks < 4; ks++) {
        unsigned a[4][4], b[4][2];
#pragma unroll
        for (int i = 0; i < 4; i++) {
            const float* ap = As + (wm * 64 + i * 16 + g) * LDA + ks * 8;
            a[i][0] = __float_as_uint(ftf(ap[t]));
            a[i][1] = __float_as_uint(ftf(ap[8 * LDA + t]));
            a[i][2] = __float_as_uint(ftf(ap[t + 4]));
            a[i][3] = __float_as_uint(ftf(ap[8 * LDA + t + 4]));
        }
#pragma unroll
        for (int j = 0; j < 4; j++) {
            const float* bp = Bs + (ks * 8) * LDB + wn * 32 + j * 8 + g;
            b[j][0] = __float_as_uint(ftf(bp[t * LDB]));
            b[j][1] = __float_as_uint(ftf(bp[(t + 4) * LDB]));
        }
#pragma unroll
        for (int i = 0; i < 4; i++)
#pragma unroll
            for (int j = 0; j < 4; j++)
                mma_tf32(acc[i][j], a[i][0], a[i][1], a[i][2], a[i][3],
                         b[j][0], b[j][1]);
    }
}

__device__ __forceinline__
void gemm_body(const float* __restrict__ A, const float* __restrict__ Bw,
               float* __restrict__ C, bool splitHeads)
{
    float* As = gsm;                         // [3][128][LDA]
    float* Bs = gsm + 3 * AS_STAGE;          // [3][32][LDB]
    const int tid  = threadIdx.x;
    const int wid  = tid >> 5;
    const int lane = tid & 31;
    const int g = lane >> 2, t = lane & 3;
    const int wm = wid >> 2, wn = wid & 3;
    const int bm = blockIdx.y << 7, bn = blockIdx.x << 7;

    float acc[4][4][4];
#pragma unroll
    for (int i = 0; i < 4; i++)
#pragma unroll
        for (int j = 0; j < 4; j++)
#pragma unroll
            for (int e = 0; e < 4; e++) acc[i][j][e] = 0.f;

    gemm_issue(A, Bw, As, Bs, bm, bn, 0, tid);
    gemm_issue(A, Bw, As + AS_STAGE, Bs + BS_STAGE, bm, bn, GBK, tid);

    for (int it = 0; it < GEMM_NIT - 1; it++) {
        cp_wait<1>();
        __syncthreads();
        if (it + 2 < GEMM_NIT) {
            int sb = (it + 2) % 3;
            gemm_issue(A, Bw, As + sb * AS_STAGE, Bs + sb * BS_STAGE,
                       bm, bn, (it + 2) * GBK, tid);
        }
        int s = it % 3;
        gemm_compute(As + s * AS_STAGE, Bs + s * BS_STAGE, acc, wm, wn, g, t);
    }
    cp_wait<0>();
    __syncthreads();
    {
        int s = (GEMM_NIT - 1) % 3;
        gemm_compute(As + s * AS_STAGE, Bs + s * BS_STAGE, acc, wm, wn, g, t);
    }

    // Epilogue: fragment float2 stores straight to gmem
#pragma unroll
    for (int i = 0; i < 4; i++) {
        int m0 = bm + wm * 64 + i * 16;
#pragma unroll
        for (int j = 0; j < 4; j++) {
            int col = bn + wn * 32 + j * 8 + 2 * t;
            int r0 = m0 + g, r1 = m0 + 8 + g;
            if (splitHeads) {
                int h = (col >> 6) & (NH - 1), d = col & (HD - 1);
                int b0r = r0 >> 11, t0 = r0 & (T_ - 1);
                int b1r = r1 >> 11, t1 = r1 & (T_ - 1);
                *(float2*)&C[((size_t)(b0r * NH + h) * T_ + t0) * HD + d] =
                    make_float2(acc[i][j][0], acc[i][j][1]);
                *(float2*)&C[((size_t)(b1r * NH + h) * T_ + t1) * HD + d] =
                    make_float2(acc[i][j][2], acc[i][j][3]);
            } else {
                *(float2*)&C[(size_t)r0 * DM + col] =
                    make_float2(acc[i][j][0], acc[i][j][1]);
                *(float2*)&C[(size_t)r1 * DM + col] =
                    make_float2(acc[i][j][2], acc[i][j][3]);
            }
        }
    }
}

__global__ __launch_bounds__(256, 2)
void qkv_gemm(const float* __restrict__ X,
              const float* __restrict__ Wq, const float* __restrict__ Wk,
              const float* __restrict__ Wv,
              float* __restrict__ Q, float* __restrict__ K, float* __restrict__ V)
{
    const float* W; float* C;
    if (blockIdx.z == 0)      { W = Wq; C = Q; }
    else if (blockIdx.z == 1) { W = Wk; C = K; }
    else                      { W = Wv; C = V; }
    gemm_body(X, W, C, true);
}

__global__ __launch_bounds__(256, 2)
void oproj_gemm(const float* __restrict__ A, const float* __restrict__ W,
                float* __restrict__ C)
{
    gemm_body(A, W, C, false);
}

// ---------------------------------------------------------------------------
// Fused per-head RMSNorm + RoPE, in place on [B,H,T,hd]. One warp per row.
// ---------------------------------------------------------------------------
__global__ __launch_bounds__(256)
void rmsrope_kernel(float* __restrict__ X, const float* __restrict__ w)
{
    int row = blockIdx.x * 8 + (threadIdx.x >> 5);
    int lane = threadIdx.x & 31;
    float* p = X + (size_t)row * HD;
    float x1 = p[lane], x2 = p[lane + 32];
    float ss = x1 * x1 + x2 * x2;
#pragma unroll
    for (int off = 16; off; off >>= 1)
        ss += __shfl_xor_sync(0xffffffffu, ss, off);
    float rms = rsqrtf(ss * (1.0f / HD) + 1e-6f);
    float n1 = x1 * rms * w[lane];
    float n2 = x2 * rms * w[lane + 32];
    int t = row & (T_ - 1);
    float freq = (float)t * powf(10000.0f, -(float)(2 * lane) * (1.0f / HD));
    float sn, cs;
    sincosf(freq, &sn, &cs);
    p[lane]      = n1 * cs - n2 * sn;
    p[lane + 32] = n2 * cs + n1 * sn;
}

// ---------------------------------------------------------------------------
// Flash attention v2: raw mma.m16n8k8 tf32, register-resident softmax/P/O.
// K/V tiles pre-converted to tf32 IN PLACE once per tile (removes the 8x
// redundant per-warp cvt chains from the MMA operand reads).
// ---------------------------------------------------------------------------
extern __shared__ float fsm[];
__global__ __launch_bounds__(256, 2)
void flash_kernel(const float* __restrict__ Q, const float* __restrict__ K,
                  const float* __restrict__ V, float* __restrict__ O)
{
    float* Qs = fsm;                              // [128][LDQ]
    float* Ks = Qs + BR * LDQ;                    // [2][64][LDK]
    float* Vs = Ks + 2 * BC * LDK;                // [2][64][LDV]

    const int tid  = threadIdx.x;
    const int wid  = tid >> 5;
    const int lane = tid & 31;
    const int g = lane >> 2, t = lane & 3;
    const int qt = gridDim.x - 1 - blockIdx.x;    // heavy tiles first
    const int q0 = qt << 7;
    const int bh = blockIdx.y;
    const float* Qg = Q + ((size_t)bh * T_ + q0) * HD;
    const float* Kg = K + (size_t)bh * T_ * HD;
    const float* Vg = V + (size_t)bh * T_ * HD;

    const int nkt = 2 * (qt + 1);

    // Prologue: issue K/V tile 0 via cp.async (raw fp32)
    {
        float* Kd = Ks; float* Vd = Vs;
#pragma unroll
        for (int p4 = 0; p4 < 4; p4++) {
            int f = tid + (p4 << 8);
            int r = f >> 4, c = (f & 15) << 2;
            cp_async16(&Kd[r * LDK + c], &Kg[(size_t)r * HD + c]);
            cp_async16(&Vd[r * LDV + c], &Vg[(size_t)r * HD + c]);
        }
        cp_commit();
    }

    // Load Q (scale 1/8 folded in — exact power of 2, then tf32 RN)
    for (int f = tid; f < BR * HD / 4; f += 256) {
        int r = f >> 4, c = (f & 15) << 2;
        float4 q4 = *(const float4*)&Qg[(size_t)r * HD + c];
        *(float4*)&Qs[r * LDQ + c] =
            make_float4(ftf(q4.x * 0.125f), ftf(q4.y * 0.125f),
                        ftf(q4.z * 0.125f), ftf(q4.w * 0.125f));
    }

    float m0 = -1e30f, m1 = -1e30f, l0 = 0.f, l1 = 0.f;
    float o[8][4];
#pragma unroll
    for (int j = 0; j < 8; j++)
#pragma unroll
        for (int e = 0; e < 4; e++) o[j][e] = 0.f;

    const int qi0 = q0 + wid * 16 + g;
    const int qrow_base = wid * 16 + g;

    for (int kt = 0; kt < nkt; kt++) {
        const int k0 = kt << 6;
        const int s = kt & 1;
        float* Kd = Ks + s * BC * LDK;
        float* Vd = Vs + s * BC * LDV;

        cp_wait<0>();
        __syncthreads();        // tile kt arrived; all warps done with buf s^1

        if (kt + 1 < nkt) {     // prefetch next tile into the other buffer
            const int kn = (kt + 1) << 6;
            float* Kn = Ks + (s ^ 1) * BC * LDK;
            float* Vn = Vs + (s ^ 1) * BC * LDV;
#pragma unroll
            for (int p4 = 0; p4 < 4; p4++) {
                int f = tid + (p4 << 8);
                int r = f >> 4, c = (f & 15) << 2;
                cp_async16(&Kn[r * LDK + c], &Kg[(size_t)(kn + r) * HD + c]);
                cp_async16(&Vn[r * LDV + c], &Vg[(size_t)(kn + r) * HD + c]);
            }
            cp_commit();
        }

        // In-place tf32 RN conversion of the arrived K/V tile (once per tile)
#pragma unroll
        for (int p4 = 0; p4 < 4; p4++) {
            int f = tid + (p4 << 8);
            int r = f >> 4, c = (f & 15) << 2;
            float4 kv = *(float4*)&Kd[r * LDK + c];
            *(float4*)&Kd[r * LDK + c] =
                make_float4(ftf(kv.x), ftf(kv.y), ftf(kv.z), ftf(kv.w));
            float4 vv = *(float4*)&Vd[r * LDV + c];
            *(float4*)&Vd[r * LDV + c] =
                make_float4(ftf(vv.x), ftf(vv.y), ftf(vv.z), ftf(vv.w));
        }
        __syncthreads();        // converted data visible to all warps

        // ---- S = Q @ K^T ----
        float sc[8][4];
#pragma unroll
        for (int j = 0; j < 8; j++)
#pragma unroll
            for (int e = 0; e < 4; e++) sc[j][e] = 0.f;

#pragma unroll
        for (int d0 = 0; d0 < HD; d0 += 8) {
            const float* qrow0 = &Qs[(wid * 16 + g) * LDQ + d0];
            unsigned a0 = __float_as_uint(qrow0[t]);
            unsigned a1 = __float_as_uint(qrow0[8 * LDQ + t]);
            unsigned a2 = __float_as_uint(qrow0[t + 4]);
            unsigned a3 = __float_as_uint(qrow0[8 * LDQ + t + 4]);
#pragma unroll
            for (int j = 0; j < 8; j++) {
                const float* krow = &Kd[(8 * j + g) * LDK + d0];
                unsigned b0 = __float_as_uint(krow[t]);
                unsigned b1 = __float_as_uint(krow[t + 4]);
                mma_tf32(sc[j], a0, a1, a2, a3, b0, b1);
            }
        }

        // ---- mask + online softmax (registers) ----
        if (kt >= nkt - 2) {
#pragma unroll
            for (int j = 0; j < 8; j++) {
                int ki = k0 + 8 * j + 2 * t;
                if (ki     > qi0)     sc[j][0] = -1e30f;
                if (ki + 1 > qi0)     sc[j][1] = -1e30f;
                if (ki     > qi0 + 8) sc[j][2] = -1e30f;
                if (ki + 1 > qi0 + 8) sc[j][3] = -1e30f;
            }
        }

        float mx0 = -1e30f, mx1 = -1e30f;
#pragma unroll
        for (int j = 0; j < 8; j++) {
            mx0 = fmaxf(mx0, fmaxf(sc[j][0], sc[j][1]));
            mx1 = fmaxf(mx1, fmaxf(sc[j][2], sc[j][3]));
        }
        mx0 = fmaxf(mx0, __shfl_xor_sync(0xffffffffu, mx0, 1));
        mx0 = fmaxf(mx0, __shfl_xor_sync(0xffffffffu, mx0, 2));
        mx1 = fmaxf(mx1, __shfl_xor_sync(0xffffffffu, mx1, 1));
        mx1 = fmaxf(mx1, __shfl_xor_sync(0xffffffffu, mx1, 2));

        float nm0 = fmaxf(m0, mx0), nm1 = fmaxf(m1, mx1);
        float al0 = __expf(m0 - nm0), al1 = __expf(m1 - nm1);
        m0 = nm0; m1 = nm1;

        float sum0 = 0.f, sum1 = 0.f;
#pragma unroll
        for (int j = 0; j < 8; j++) {
            float p0 = __expf(sc[j][0] - nm0);
            float p1 = __expf(sc[j][1] - nm0);
            float p2 = __expf(sc[j][2] - nm1);
            float p3 = __expf(sc[j][3] - nm1);
            sum0 += p0 + p1; sum1 += p2 + p3;
            sc[j][0] = ftf(p0); sc[j][1] = ftf(p1);
            sc[j][2] = ftf(p2); sc[j][3] = ftf(p3);
        }
        sum0 += __shfl_xor_sync(0xffffffffu, sum0, 1);
        sum0 += __shfl_xor_sync(0xffffffffu, sum0, 2);
        sum1 += __shfl_xor_sync(0xffffffffu, sum1, 1);
        sum1 += __shfl_xor_sync(0xffffffffu, sum1, 2);
        l0 = l0 * al0 + sum0;
        l1 = l1 * al1 + sum1;

#pragma unroll
        for (int j = 0; j < 8; j++) {
            o[j][0] *= al0; o[j][1] *= al0;
            o[j][2] *= al1; o[j][3] *= al1;
        }

        // ---- PV: O += P @ V ----
        const int src0 = (lane & ~3) | (t >> 1);
        const int src2 = src0 | 2;
        const bool odd = (lane & 1);
#pragma unroll
        for (int ks = 0; ks < 8; ks++) {
            float v00 = __shfl_sync(0xffffffffu, sc[ks][0], src0);
            float v01 = __shfl_sync(0xffffffffu, sc[ks][1], src0);
            float v10 = __shfl_sync(0xffffffffu, sc[ks][2], src0);
            float v11 = __shfl_sync(0xffffffffu, sc[ks][3], src0);
            float v20 = __shfl_sync(0xffffffffu, sc[ks][0], src2);
            float v21 = __shfl_sync(0xffffffffu, sc[ks][1], src2);
            float v30 = __shfl_sync(0xffffffffu, sc[ks][2], src2);
            float v31 = __shfl_sync(0xffffffffu, sc[ks][3], src2);
            unsigned a0 = __float_as_uint(odd ? v01 : v00);
            unsigned a1 = __float_as_uint(odd ? v11 : v10);
            unsigned a2 = __float_as_uint(odd ? v21 : v20);
            unsigned a3 = __float_as_uint(odd ? v31 : v30);
#pragma unroll
            for (int jd = 0; jd < 8; jd++) {
                unsigned b0 = __float_as_uint(Vd[(8 * ks + t) * LDV + 8 * jd + g]);
                unsigned b1 = __float_as_uint(Vd[(8 * ks + t + 4) * LDV + 8 * jd + g]);
                mma_tf32(o[jd], a0, a1, a2, a3, b0, b1);
            }
        }
    }

    // Epilogue: normalize, write to [B,T,D]
    const int b = bh >> 4, h = bh & (NH - 1);
    const float inv0 = 1.0f / l0, inv1 = 1.0f / l1;
    float* Og0 = O + ((size_t)(b * T_ + q0 + qrow_base)) * DM + h * HD;
    float* Og1 = Og0 + (size_t)8 * DM;
#pragma unroll
    for (int jd = 0; jd < 8; jd++) {
        int col = 8 * jd + 2 * t;
        *(float2*)&Og0[col] = make_float2(o[jd][0] * inv0, o[jd][1] * inv0);
        *(float2*)&Og1[col] = make_float2(o[jd][2] * inv1, o[jd][3] * inv1);
    }
}

// ---------------------------------------------------------------------------
extern "C" void kernel_launch(void* const* d_in, const int* in_sizes, int n_in,
                              void* d_out, int out_size)
{
    (void)in_sizes; (void)n_in; (void)out_size;
    const float* x  = (const float*)d_in[0];
    const float* Wq = (const float*)d_in[1];
    const float* Wk = (const float*)d_in[2];
    const float* Wv = (const float*)d_in[3];
    const float* Wo = (const float*)d_in[4];
    const float* qw = (const float*)d_in[5];
    const float* kw = (const float*)d_in[6];
    float* out = (float*)d_out;

    float *qp, *kp, *vp, *ap;
    cudaGetSymbolAddress((void**)&qp, g_q);
    cudaGetSymbolAddress((void**)&kp, g_k);
    cudaGetSymbolAddress((void**)&vp, g_v);
    cudaGetSymbolAddress((void**)&ap, g_attn);

    cudaFuncSetAttribute(qkv_gemm,
                         cudaFuncAttributeMaxDynamicSharedMemorySize, GEMM_SMEM);
    cudaFuncSetAttribute(oproj_gemm,
                         cudaFuncAttributeMaxDynamicSharedMemorySize, GEMM_SMEM);

    const int FLASH_SMEM = (BR * LDQ + 2 * BC * LDK + 2 * BC * LDV) * 4;  // 106496
    cudaFuncSetAttribute(flash_kernel,
                         cudaFuncAttributeMaxDynamicSharedMemorySize, FLASH_SMEM);

    dim3 gq(DM / 128, ROWS / 128, 3);   // (8, 32, 3)
    qkv_gemm<<<gq, 256, GEMM_SMEM>>>(x, Wq, Wk, Wv, qp, kp, vp);

    rmsrope_kernel<<<B_ * NH * T_ / 8, 256>>>(qp, qw);
    rmsrope_kernel<<<B_ * NH * T_ / 8, 256>>>(kp, kw);

    flash_kernel<<<dim3(T_ / BR, B_ * NH), 256, FLASH_SMEM>>>(qp, kp, vp, ap);

    dim3 go(DM / 128, ROWS / 128);      // (8, 32)
    oproj_gemm<<<go, 256, GEMM_SMEM>>>(ap, Wo, out);
}

// round 9
// speedup vs baseline: 2.5999x; 1.0562x over previous
#include <cuda_runtime.h>
#include <mma.h>
#include <math.h>

using namespace nvcuda;

#define DM 1024
#define NH 16
#define HD 64
#define B_ 2
#define T_ 2048
#define ROWS (B_*T_)

#define BR 128
#define BC 64
#define LDQ 68
#define LDK 68
#define LDV 72

// GEMM pipeline geometry (BK=32, 3 stages)
#define GBK 32
#define LDA 36
#define LDB 136
#define AS_STAGE (128*LDA)
#define BS_STAGE (GBK*LDB)
#define GEMM_NIT (1024/GBK)
#define GEMM_SMEM ((3*(AS_STAGE+BS_STAGE))*4)   // 107520 B

// Scratch (static device globals — allocation-free per harness rules)
__device__ float g_q[(size_t)B_*NH*T_*HD];     // [B,H,T,hd] (tf32-valued after rmsrope)
__device__ float g_k[(size_t)B_*NH*T_*HD];
__device__ float g_v[(size_t)B_*NH*T_*HD];     // tf32-valued from qkv epilogue
__device__ float g_attn[(size_t)ROWS*DM];      // [B,T,D]    (tf32-valued from flash)
__device__ float g_xt[(size_t)ROWS*DM];        // X  pre-converted to tf32
__device__ float g_wt[4][(size_t)DM*DM];       // Wq,Wk,Wv,Wo pre-converted to tf32

__device__ __forceinline__ float ftf(float x) { return wmma::__float_to_tf32(x); }

__device__ __forceinline__ void cp_async16(void* smem_ptr, const void* gmem_ptr) {
    unsigned int saddr = (unsigned int)__cvta_generic_to_shared(smem_ptr);
    asm volatile("cp.async.cg.shared.global [%0], [%1], 16;\n"
                 :: "r"(saddr), "l"(gmem_ptr));
}
__device__ __forceinline__ void cp_commit() {
    asm volatile("cp.async.commit_group;\n");
}
template<int N>
__device__ __forceinline__ void cp_wait() {
    asm volatile("cp.async.wait_group %0;\n" :: "n"(N));
}

// mma.m16n8k8 tf32. g=lane>>2, t=lane&3.
//   A: a0=(g,t) a1=(g+8,t) a2=(g,t+4) a3=(g+8,t+4)
//   B: b0=(k=t,n=g) b1=(k=t+4,n=g)
//   C: c0=(g,2t) c1=(g,2t+1) c2=(g+8,2t) c3=(g+8,2t+1)
__device__ __forceinline__
void mma_tf32(float* c, unsigned a0, unsigned a1, unsigned a2, unsigned a3,
              unsigned b0, unsigned b1)
{
    asm volatile(
        "mma.sync.aligned.m16n8k8.row.col.f32.tf32.tf32.f32 "
        "{%0,%1,%2,%3},{%4,%5,%6,%7},{%8,%9},{%0,%1,%2,%3};\n"
        : "+f"(c[0]), "+f"(c[1]), "+f"(c[2]), "+f"(c[3])
        : "r"(a0), "r"(a1), "r"(a2), "r"(a3), "r"(b0), "r"(b1));
}

// ---------------------------------------------------------------------------
// Pre-convert fp32 -> tf32-valued fp32 (RN), grid-stride float4.
// ---------------------------------------------------------------------------
__global__ __launch_bounds__(256)
void cvt_kernel(const float* __restrict__ src, float* __restrict__ dst, int n4)
{
    int i = blockIdx.x * blockDim.x + threadIdx.x;
    if (i < n4) {
        float4 v = *(const float4*)&src[i * 4];
        *(float4*)&dst[i * 4] = make_float4(ftf(v.x), ftf(v.y), ftf(v.z), ftf(v.w));
    }
}

// ---------------------------------------------------------------------------
// tf32 raw-mma GEMM on PRE-CONVERTED operands (no cvt in hot loop).
// C[M,N]=A[M,K]@B[K,N], K=N=1024. 128x128 tile, BK=32, 3-stage cp.async.
// cvtOut: round the fp32 accumulator to tf32 on store (for V).
// ---------------------------------------------------------------------------
extern __shared__ float gsm[];

__device__ __forceinline__
void gemm_issue(const float* __restrict__ A, const float* __restrict__ Bw,
                float* As, float* Bs, int bm, int bn, int k0, int tid)
{
#pragma unroll
    for (int p = 0; p < 4; p++) {
        int f = tid + (p << 8);
        int ar = f >> 3, ac = (f & 7) << 2;
        cp_async16(&As[ar * LDA + ac], &A[(size_t)(bm + ar) * 1024 + k0 + ac]);
        int br = f >> 5, bc = (f & 31) << 2;
        cp_async16(&Bs[br * LDB + bc], &Bw[(size_t)(k0 + br) * 1024 + bn + bc]);
    }
    cp_commit();
}

__device__ __forceinline__
void gemm_compute(const float* As, const float* Bs, float acc[4][4][4],
                  int wm, int wn, int g, int t)
{
#pragma unroll
    for (int ks = 0; ks < 4; ks++) {
        unsigned a[4][4], b[4][2];
#pragma unroll
        for (int i = 0; i < 4; i++) {
            const float* ap = As + (wm * 64 + i * 16 + g) * LDA + ks * 8;
            a[i][0] = __float_as_uint(ap[t]);
            a[i][1] = __float_as_uint(ap[8 * LDA + t]);
            a[i][2] = __float_as_uint(ap[t + 4]);
            a[i][3] = __float_as_uint(ap[8 * LDA + t + 4]);
        }
#pragma unroll
        for (int j = 0; j < 4; j++) {
            const float* bp = Bs + (ks * 8) * LDB + wn * 32 + j * 8 + g;
            b[j][0] = __float_as_uint(bp[t * LDB]);
            b[j][1] = __float_as_uint(bp[(t + 4) * LDB]);
        }
#pragma unroll
        for (int i = 0; i < 4; i++)
#pragma unroll
            for (int j = 0; j < 4; j++)
                mma_tf32(acc[i][j], a[i][0], a[i][1], a[i][2], a[i][3],
                         b[j][0], b[j][1]);
    }
}

__device__ __forceinline__
void gemm_body(const float* __restrict__ A, const float* __restrict__ Bw,
               float* __restrict__ C, bool splitHeads, bool cvtOut)
{
    float* As = gsm;
    float* Bs = gsm + 3 * AS_STAGE;
    const int tid  = threadIdx.x;
    const int wid  = tid >> 5;
    const int lane = tid & 31;
    const int g = lane >> 2, t = lane & 3;
    const int wm = wid >> 2, wn = wid & 3;
    const int bm = blockIdx.y << 7, bn = blockIdx.x << 7;

    float acc[4][4][4];
#pragma unroll
    for (int i = 0; i < 4; i++)
#pragma unroll
        for (int j = 0; j < 4; j++)
#pragma unroll
            for (int e = 0; e < 4; e++) acc[i][j][e] = 0.f;

    gemm_issue(A, Bw, As, Bs, bm, bn, 0, tid);
    gemm_issue(A, Bw, As + AS_STAGE, Bs + BS_STAGE, bm, bn, GBK, tid);

    for (int it = 0; it < GEMM_NIT - 1; it++) {
        cp_wait<1>();
        __syncthreads();
        if (it + 2 < GEMM_NIT) {
            int sb = (it + 2) % 3;
            gemm_issue(A, Bw, As + sb * AS_STAGE, Bs + sb * BS_STAGE,
                       bm, bn, (it + 2) * GBK, tid);
        }
        int s = it % 3;
        gemm_compute(As + s * AS_STAGE, Bs + s * BS_STAGE, acc, wm, wn, g, t);
    }
    cp_wait<0>();
    __syncthreads();
    {
        int s = (GEMM_NIT - 1) % 3;
        gemm_compute(As + s * AS_STAGE, Bs + s * BS_STAGE, acc, wm, wn, g, t);
    }

#pragma unroll
    for (int i = 0; i < 4; i++) {
        int m0 = bm + wm * 64 + i * 16;
#pragma unroll
        for (int j = 0; j < 4; j++) {
            int col = bn + wn * 32 + j * 8 + 2 * t;
            int r0 = m0 + g, r1 = m0 + 8 + g;
            float2 lo = make_float2(acc[i][j][0], acc[i][j][1]);
            float2 hi = make_float2(acc[i][j][2], acc[i][j][3]);
            if (cvtOut) {
                lo.x = ftf(lo.x); lo.y = ftf(lo.y);
                hi.x = ftf(hi.x); hi.y = ftf(hi.y);
            }
            if (splitHeads) {
                int h = (col >> 6) & (NH - 1), d = col & (HD - 1);
                int b0r = r0 >> 11, t0 = r0 & (T_ - 1);
                int b1r = r1 >> 11, t1 = r1 & (T_ - 1);
                *(float2*)&C[((size_t)(b0r * NH + h) * T_ + t0) * HD + d] = lo;
                *(float2*)&C[((size_t)(b1r * NH + h) * T_ + t1) * HD + d] = hi;
            } else {
                *(float2*)&C[(size_t)r0 * DM + col] = lo;
                *(float2*)&C[(size_t)r1 * DM + col] = hi;
            }
        }
    }
}

__global__ __launch_bounds__(256, 2)
void qkv_gemm(const float* __restrict__ X,
              const float* __restrict__ Wq, const float* __restrict__ Wk,
              const float* __restrict__ Wv,
              float* __restrict__ Q, float* __restrict__ K, float* __restrict__ V)
{
    if (blockIdx.z == 0)      gemm_body(X, Wq, Q, true, false);
    else if (blockIdx.z == 1) gemm_body(X, Wk, K, true, false);
    else                      gemm_body(X, Wv, V, true, true);   // V: tf32 out
}

__global__ __launch_bounds__(256, 2)
void oproj_gemm(const float* __restrict__ A, const float* __restrict__ W,
                float* __restrict__ C)
{
    gemm_body(A, W, C, false, false);
}

// ---------------------------------------------------------------------------
// Fused per-head RMSNorm + RoPE, in place. Output rounded to tf32; `scale`
// (1/8 for Q, 1 for K) folded in before the rounding.
// ---------------------------------------------------------------------------
__global__ __launch_bounds__(256)
void rmsrope_kernel(float* __restrict__ X, const float* __restrict__ w,
                    float scale)
{
    int row = blockIdx.x * 8 + (threadIdx.x >> 5);
    int lane = threadIdx.x & 31;
    float* p = X + (size_t)row * HD;
    float x1 = p[lane], x2 = p[lane + 32];
    float ss = x1 * x1 + x2 * x2;
#pragma unroll
    for (int off = 16; off; off >>= 1)
        ss += __shfl_xor_sync(0xffffffffu, ss, off);
    float rms = rsqrtf(ss * (1.0f / HD) + 1e-6f);
    float n1 = x1 * rms * w[lane];
    float n2 = x2 * rms * w[lane + 32];
    int t = row & (T_ - 1);
    float freq = (float)t * powf(10000.0f, -(float)(2 * lane) * (1.0f / HD));
    float sn, cs;
    sincosf(freq, &sn, &cs);
    p[lane]      = ftf((n1 * cs - n2 * sn) * scale);
    p[lane + 32] = ftf((n2 * cs + n1 * sn) * scale);
}

// ---------------------------------------------------------------------------
// Flash attention v2: raw mma.m16n8k8 tf32, register-resident softmax/P/O.
// All inputs pre-converted to tf32 — ZERO conversions in the loop except P.
// One __syncthreads per key tile; cp.async double-buffered K/V.
// ---------------------------------------------------------------------------
extern __shared__ float fsm[];
__global__ __launch_bounds__(256, 2)
void flash_kernel(const float* __restrict__ Q, const float* __restrict__ K,
                  const float* __restrict__ V, float* __restrict__ O)
{
    float* Qs = fsm;                              // [128][LDQ]
    float* Ks = Qs + BR * LDQ;                    // [2][64][LDK]
    float* Vs = Ks + 2 * BC * LDK;                // [2][64][LDV]

    const int tid  = threadIdx.x;
    const int wid  = tid >> 5;
    const int lane = tid & 31;
    const int g = lane >> 2, t = lane & 3;
    const int qt = gridDim.x - 1 - blockIdx.x;    // heavy tiles first
    const int q0 = qt << 7;
    const int bh = blockIdx.y;
    const float* Qg = Q + ((size_t)bh * T_ + q0) * HD;
    const float* Kg = K + (size_t)bh * T_ * HD;
    const float* Vg = V + (size_t)bh * T_ * HD;

    const int nkt = 2 * (qt + 1);

    // Prologue: issue K/V tile 0 (already tf32-valued)
    {
#pragma unroll
        for (int p4 = 0; p4 < 4; p4++) {
            int f = tid + (p4 << 8);
            int r = f >> 4, c = (f & 15) << 2;
            cp_async16(&Ks[r * LDK + c], &Kg[(size_t)r * HD + c]);
            cp_async16(&Vs[r * LDV + c], &Vg[(size_t)r * HD + c]);
        }
        cp_commit();
    }

    // Load Q tile (already tf32-valued, 1/8 scale folded in by rmsrope)
    for (int f = tid; f < BR * HD / 4; f += 256) {
        int r = f >> 4, c = (f & 15) << 2;
        *(float4*)&Qs[r * LDQ + c] = *(const float4*)&Qg[(size_t)r * HD + c];
    }

    float m0 = -1e30f, m1 = -1e30f, l0 = 0.f, l1 = 0.f;
    float o[8][4];
#pragma unroll
    for (int j = 0; j < 8; j++)
#pragma unroll
        for (int e = 0; e < 4; e++) o[j][e] = 0.f;

    const int qi0 = q0 + wid * 16 + g;
    const int qrow_base = wid * 16 + g;

    for (int kt = 0; kt < nkt; kt++) {
        const int k0 = kt << 6;
        const int s = kt & 1;
        float* Kd = Ks + s * BC * LDK;
        float* Vd = Vs + s * BC * LDV;

        cp_wait<0>();
        __syncthreads();

        if (kt + 1 < nkt) {
            const int kn = (kt + 1) << 6;
            float* Kn = Ks + (s ^ 1) * BC * LDK;
            float* Vn = Vs + (s ^ 1) * BC * LDV;
#pragma unroll
            for (int p4 = 0; p4 < 4; p4++) {
                int f = tid + (p4 << 8);
                int r = f >> 4, c = (f & 15) << 2;
                cp_async16(&Kn[r * LDK + c], &Kg[(size_t)(kn + r) * HD + c]);
                cp_async16(&Vn[r * LDV + c], &Vg[(size_t)(kn + r) * HD + c]);
            }
            cp_commit();
        }

        // ---- S = Q @ K^T ----
        float sc[8][4];
#pragma unroll
        for (int j = 0; j < 8; j++)
#pragma unroll
            for (int e = 0; e < 4; e++) sc[j][e] = 0.f;

#pragma unroll
        for (int d0 = 0; d0 < HD; d0 += 8) {
            const float* qrow0 = &Qs[(wid * 16 + g) * LDQ + d0];
            unsigned a0 = __float_as_uint(qrow0[t]);
            unsigned a1 = __float_as_uint(qrow0[8 * LDQ + t]);
            unsigned a2 = __float_as_uint(qrow0[t + 4]);
            unsigned a3 = __float_as_uint(qrow0[t + 4 + 8 * LDQ]);
#pragma unroll
            for (int j = 0; j < 8; j++) {
                const float* krow = &Kd[(8 * j + g) * LDK + d0];
                unsigned b0 = __float_as_uint(krow[t]);
                unsigned b1 = __float_as_uint(krow[t + 4]);
                mma_tf32(sc[j], a0, a1, a2, a3, b0, b1);
            }
        }

        // ---- mask + online softmax (registers) ----
        if (kt >= nkt - 2) {
#pragma unroll
            for (int j = 0; j < 8; j++) {
                int ki = k0 + 8 * j + 2 * t;
                if (ki     > qi0)     sc[j][0] = -1e30f;
                if (ki + 1 > qi0)     sc[j][1] = -1e30f;
                if (ki     > qi0 + 8) sc[j][2] = -1e30f;
                if (ki + 1 > qi0 + 8) sc[j][3] = -1e30f;
            }
        }

        float mx0 = -1e30f, mx1 = -1e30f;
#pragma unroll
        for (int j = 0; j < 8; j++) {
            mx0 = fmaxf(mx0, fmaxf(sc[j][0], sc[j][1]));
            mx1 = fmaxf(mx1, fmaxf(sc[j][2], sc[j][3]));
        }
        mx0 = fmaxf(mx0, __shfl_xor_sync(0xffffffffu, mx0, 1));
        mx0 = fmaxf(mx0, __shfl_xor_sync(0xffffffffu, mx0, 2));
        mx1 = fmaxf(mx1, __shfl_xor_sync(0xffffffffu, mx1, 1));
        mx1 = fmaxf(mx1, __shfl_xor_sync(0xffffffffu, mx1, 2));

        float nm0 = fmaxf(m0, mx0), nm1 = fmaxf(m1, mx1);
        float al0 = __expf(m0 - nm0), al1 = __expf(m1 - nm1);
        m0 = nm0; m1 = nm1;

        float sum0 = 0.f, sum1 = 0.f;
#pragma unroll
        for (int j = 0; j < 8; j++) {
            float p0 = __expf(sc[j][0] - nm0);
            float p1 = __expf(sc[j][1] - nm0);
            float p2 = __expf(sc[j][2] - nm1);
            float p3 = __expf(sc[j][3] - nm1);
            sum0 += p0 + p1; sum1 += p2 + p3;
            sc[j][0] = ftf(p0); sc[j][1] = ftf(p1);
            sc[j][2] = ftf(p2); sc[j][3] = ftf(p3);
        }
        sum0 += __shfl_xor_sync(0xffffffffu, sum0, 1);
        sum0 += __shfl_xor_sync(0xffffffffu, sum0, 2);
        sum1 += __shfl_xor_sync(0xffffffffu, sum1, 1);
        sum1 += __shfl_xor_sync(0xffffffffu, sum1, 2);
        l0 = l0 * al0 + sum0;
        l1 = l1 * al1 + sum1;

#pragma unroll
        for (int j = 0; j < 8; j++) {
            o[j][0] *= al0; o[j][1] *= al0;
            o[j][2] *= al1; o[j][3] *= al1;
        }

        // ---- PV: O += P @ V ----
        const int src0 = (lane & ~3) | (t >> 1);
        const int src2 = src0 | 2;
        const bool odd = (lane & 1);
#pragma unroll
        for (int ks = 0; ks < 8; ks++) {
            float v00 = __shfl_sync(0xffffffffu, sc[ks][0], src0);
            float v01 = __shfl_sync(0xffffffffu, sc[ks][1], src0);
            float v10 = __shfl_sync(0xffffffffu, sc[ks][2], src0);
            float v11 = __shfl_sync(0xffffffffu, sc[ks][3], src0);
            float v20 = __shfl_sync(0xffffffffu, sc[ks][0], src2);
            float v21 = __shfl_sync(0xffffffffu, sc[ks][1], src2);
            float v30 = __shfl_sync(0xffffffffu, sc[ks][2], src2);
            float v31 = __shfl_sync(0xffffffffu, sc[ks][3], src2);
            unsigned a0 = __float_as_uint(odd ? v01 : v00);
            unsigned a1 = __float_as_uint(odd ? v11 : v10);
            unsigned a2 = __float_as_uint(odd ? v21 : v20);
            unsigned a3 = __float_as_uint(odd ? v31 : v30);
#pragma unroll
            for (int jd = 0; jd < 8; jd++) {
                unsigned b0 = __float_as_uint(Vd[(8 * ks + t) * LDV + 8 * jd + g]);
                unsigned b1 = __float_as_uint(Vd[(8 * ks + t + 4) * LDV + 8 * jd + g]);
                mma_tf32(o[jd], a0, a1, a2, a3, b0, b1);
            }
        }
    }

    // Epilogue: normalize, round to tf32 (feeds cvt-free O projection)
    const int b = bh >> 4, h = bh & (NH - 1);
    const float inv0 = 1.0f / l0, inv1 = 1.0f / l1;
    float* Og0 = O + ((size_t)(b * T_ + q0 + qrow_base)) * DM + h * HD;
    float* Og1 = Og0 + (size_t)8 * DM;
#pragma unroll
    for (int jd = 0; jd < 8; jd++) {
        int col = 8 * jd + 2 * t;
        *(float2*)&Og0[col] = make_float2(ftf(o[jd][0] * inv0), ftf(o[jd][1] * inv0));
        *(float2*)&Og1[col] = make_float2(ftf(o[jd][2] * inv1), ftf(o[jd][3] * inv1));
    }
}

// ---------------------------------------------------------------------------
extern "C" void kernel_launch(void* const* d_in, const int* in_sizes, int n_in,
                              void* d_out, int out_size)
{
    (void)in_sizes; (void)n_in; (void)out_size;
    const float* x  = (const float*)d_in[0];
    const float* Wq = (const float*)d_in[1];
    const float* Wk = (const float*)d_in[2];
    const float* Wv = (const float*)d_in[3];
    const float* Wo = (const float*)d_in[4];
    const float* qw = (const float*)d_in[5];
    const float* kw = (const float*)d_in[6];
    float* out = (float*)d_out;

    float *qp, *kp, *vp, *ap, *xt, *wt;
    cudaGetSymbolAddress((void**)&qp, g_q);
    cudaGetSymbolAddress((void**)&kp, g_k);
    cudaGetSymbolAddress((void**)&vp, g_v);
    cudaGetSymbolAddress((void**)&ap, g_attn);
    cudaGetSymbolAddress((void**)&xt, g_xt);
    cudaGetSymbolAddress((void**)&wt, g_wt);

    cudaFuncSetAttribute(qkv_gemm,
                         cudaFuncAttributeMaxDynamicSharedMemorySize, GEMM_SMEM);
    cudaFuncSetAttribute(oproj_gemm,
                         cudaFuncAttributeMaxDynamicSharedMemorySize, GEMM_SMEM);

    const int FLASH_SMEM = (BR * LDQ + 2 * BC * LDK + 2 * BC * LDV) * 4;  // 106496
    cudaFuncSetAttribute(flash_kernel,
                         cudaFuncAttributeMaxDynamicSharedMemorySize, FLASH_SMEM);

    // Pre-convert X and weights to tf32 (RN, once)
    const int NX4 = ROWS * DM / 4, NW4 = DM * DM / 4;
    cvt_kernel<<<(NX4 + 255) / 256, 256>>>(x,  xt,            NX4);
    cvt_kernel<<<(NW4 + 255) / 256, 256>>>(Wq, wt + 0 * (size_t)DM * DM, NW4);
    cvt_kernel<<<(NW4 + 255) / 256, 256>>>(Wk, wt + 1 * (size_t)DM * DM, NW4);
    cvt_kernel<<<(NW4 + 255) / 256, 256>>>(Wv, wt + 2 * (size_t)DM * DM, NW4);
    cvt_kernel<<<(NW4 + 255) / 256, 256>>>(Wo, wt + 3 * (size_t)DM * DM, NW4);

    dim3 gq(DM / 128, ROWS / 128, 3);   // (8, 32, 3)
    qkv_gemm<<<gq, 256, GEMM_SMEM>>>(xt, wt, wt + (size_t)DM * DM,
                                     wt + 2 * (size_t)DM * DM, qp, kp, vp);

    rmsrope_kernel<<<B_ * NH * T_ / 8, 256>>>(qp, qw, 0.125f);
    rmsrope_kernel<<<B_ * NH * T_ / 8, 256>>>(kp, kw, 1.0f);

    flash_kernel<<<dim3(T_ / BR, B_ * NH), 256, FLASH_SMEM>>>(qp, kp, vp, ap);

    dim3 go(DM / 128, ROWS / 128);      // (8, 32)
    oproj_gemm<<<go, 256, GEMM_SMEM>>>(ap, wt + 3 * (size_t)DM * DM, out);
}